// round 8
// baseline (speedup 1.0000x reference)
#include <cuda_runtime.h>
#include <cuda_bf16.h>
#include <cstdint>
#include <math.h>

#define N_PTS 20000
#define M_PTS 160000
#define CI 128
#define CO 64
#define GD 34
#define GSZ (GD*GD*GD)

// double-buffered stage: A 128x32 (hi+lo), B 64x32 (hi+lo), rows padded to 40 halves
#define A_HALF (128*40)          // uint16 count
#define B_HALF (64*40)
#define BUF_BYTES ((A_HALF*2 + B_HALF*2)*2)   // 30720 B per buffer
#define SMEM_DYN (2*BUF_BYTES)

// ---------------- device scratch ----------------
__device__ int      g_pgrid[GSZ];
__device__ uint32_t g_h_pk[N_PTS*CI];       // silu(gn1(x)) packed bf16 hi|lo
__device__ float    g_skip[N_PTS*CO];
__device__ float    g_mid[M_PTS*CO];        // conv1 out fp32
__device__ uint32_t g_act_pk[M_PTS*CO];     // silu(gn2(mid)) packed
__device__ uint32_t g_weffT_pk[8*8*CO*CI];  // [o][n][cout][cin] packed
__device__ uint32_t g_w2t_pk[27*CO*CO];     // [tap][cout][cin] packed
__device__ float g_sum1[CI], g_sq1[CI], g_mu1[32], g_rs1[32];
__device__ float g_sum2[CO], g_sq2[CO], g_mu2[32], g_rs2[32];

// ---------------- helpers ----------------
__device__ __forceinline__ uint32_t smem_u32(const void* p){
    uint32_t a;
    asm("{ .reg .u64 t; cvta.to.shared.u64 t, %1; cvt.u32.u64 %0, t; }" : "=r"(a) : "l"(p));
    return a;
}
__device__ __forceinline__ uint32_t pack_hl(float v){
    unsigned short h = __bfloat16_as_ushort(__float2bfloat16(v));
    float hf = __bfloat162float(__ushort_as_bfloat16(h));
    unsigned short lo = __bfloat16_as_ushort(__float2bfloat16(v - hf));
    return (uint32_t)h | ((uint32_t)lo << 16);
}
__device__ __forceinline__ void ldsm4(uint32_t* r, uint32_t addr){
    asm volatile("ldmatrix.sync.aligned.m8n8.x4.shared.b16 {%0,%1,%2,%3}, [%4];"
        : "=r"(r[0]),"=r"(r[1]),"=r"(r[2]),"=r"(r[3]) : "r"(addr));
}
__device__ __forceinline__ void mma16816(float* d, const uint32_t* a, uint32_t b0, uint32_t b1){
    asm volatile("mma.sync.aligned.m16n8k16.row.col.f32.bf16.bf16.f32 "
        "{%0,%1,%2,%3}, {%4,%5,%6,%7}, {%8,%9}, {%0,%1,%2,%3};"
        : "+f"(d[0]),"+f"(d[1]),"+f"(d[2]),"+f"(d[3])
        : "r"(a[0]),"r"(a[1]),"r"(a[2]),"r"(a[3]), "r"(b0),"r"(b1));
}
__device__ __forceinline__ void unpack_store(uint16_t* sH, uint16_t* sL, int vecIdx,
                                             uint4 v0, uint4 v1){
    uint4 h, lo;
    h.x  = __byte_perm(v0.x, v0.y, 0x5410); lo.x = __byte_perm(v0.x, v0.y, 0x7632);
    h.y  = __byte_perm(v0.z, v0.w, 0x5410); lo.y = __byte_perm(v0.z, v0.w, 0x7632);
    h.z  = __byte_perm(v1.x, v1.y, 0x5410); lo.z = __byte_perm(v1.x, v1.y, 0x7632);
    h.w  = __byte_perm(v1.z, v1.w, 0x5410); lo.w = __byte_perm(v1.z, v1.w, 0x7632);
    ((uint4*)sH)[vecIdx] = h;
    ((uint4*)sL)[vecIdx] = lo;
}

// ---------------- small kernels ----------------
__global__ void k_init(){
    int i = blockIdx.x*256 + threadIdx.x;
    if (i < GSZ) g_pgrid[i] = -1;
    if (i < CI){ g_sum1[i]=0.f; g_sq1[i]=0.f; }
    if (i < CO){ g_sum2[i]=0.f; g_sq2[i]=0.f; }
}
__global__ void k_scatter(const int* __restrict__ coords){
    int p = blockIdx.x*256 + threadIdx.x;
    if (p < N_PTS){
        int x=coords[p*4+1], y=coords[p*4+2], z=coords[p*4+3];
        g_pgrid[((x+1)*GD + (y+1))*GD + (z+1)] = p;
    }
}
__global__ void k_stats1(const float* __restrict__ xf){
    int c = threadIdx.x;
    float s=0.f, s2=0.f;
    for (int r = blockIdx.x; r < N_PTS; r += gridDim.x){
        float v = xf[r*CI + c]; s += v; s2 += v*v;
    }
    atomicAdd(&g_sum1[c], s); atomicAdd(&g_sq1[c], s2);
}
__global__ void k_fin1(){
    int g = threadIdx.x;
    if (g < 32){
        float s=0.f, s2=0.f;
        for (int j=0;j<4;j++){ s += g_sum1[g*4+j]; s2 += g_sq1[g*4+j]; }
        float inv = 1.f/(float)(N_PTS*4);
        float mu = s*inv, var = s2*inv - mu*mu;
        g_mu1[g] = mu; g_rs1[g] = rsqrtf(var + 1e-5f);
    }
}
__global__ void k_h(const float* __restrict__ xf,
                    const float* __restrict__ gma, const float* __restrict__ bta){
    int i = blockIdx.x*256 + threadIdx.x;
    int c = i & (CI-1); int g = c >> 2;
    float v = (xf[i] - g_mu1[g])*g_rs1[g]*gma[c] + bta[c];
    v = v / (1.f + expf(-v));
    g_h_pk[i] = pack_hl(v);
}
__global__ void k_weffT(const float* __restrict__ W1){
    int idx = blockIdx.x*256 + threadIdx.x;   // 8*8*128*64
    int cout = idx & 63, cin = (idx>>6)&127, n = (idx>>13)&7, o = idx>>16;
    int d0=(o>>2)&1, d1=(o>>1)&1, d2=o&1;
    int n0=(n>>2)&1, n1=(n>>1)&1, n2=n&1;
    float s = 0.f;
    for (int i=0;i<3;i++){
        int t0=d0+i-1; int p0=(t0>=2)?1:((t0>=0)?0:-1);
        if (p0 - d0 + 1 != n0) continue;
        for (int j=0;j<3;j++){
            int t1=d1+j-1; int p1=(t1>=2)?1:((t1>=0)?0:-1);
            if (p1 - d1 + 1 != n1) continue;
            for (int k=0;k<3;k++){
                int t2=d2+k-1; int p2=(t2>=2)?1:((t2>=0)?0:-1);
                if (p2 - d2 + 1 != n2) continue;
                s += W1[(((i*3+j)*3+k)*CI + cin)*CO + cout];
            }
        }
    }
    g_weffT_pk[((o*8+n)*CO + cout)*CI + cin] = pack_hl(s);
}
__global__ void k_w2t(const float* __restrict__ W2){
    int idx = blockIdx.x*256 + threadIdx.x;   // 27*64*64
    if (idx >= 27*CO*CO) return;
    int cout = idx & 63, cin = (idx>>6)&63, tap = idx>>12;
    g_w2t_pk[(tap*CO + cout)*CO + cin] = pack_hl(W2[(tap*CO + cin)*CO + cout]);
}

// ---------------- skip GEMM (scalar fp32, tiny) ----------------
__device__ __forceinline__ void mma_row(float4 a, float4 w0, float4 w1, float4 w2, float4 w3,
                                        float acc[4]){
    acc[0]=fmaf(a.x,w0.x,acc[0]); acc[0]=fmaf(a.y,w1.x,acc[0]); acc[0]=fmaf(a.z,w2.x,acc[0]); acc[0]=fmaf(a.w,w3.x,acc[0]);
    acc[1]=fmaf(a.x,w0.y,acc[1]); acc[1]=fmaf(a.y,w1.y,acc[1]); acc[1]=fmaf(a.z,w2.y,acc[1]); acc[1]=fmaf(a.w,w3.y,acc[1]);
    acc[2]=fmaf(a.x,w0.z,acc[2]); acc[2]=fmaf(a.y,w1.z,acc[2]); acc[2]=fmaf(a.z,w2.z,acc[2]); acc[2]=fmaf(a.w,w3.z,acc[2]);
    acc[3]=fmaf(a.x,w0.w,acc[3]); acc[3]=fmaf(a.y,w1.w,acc[3]); acc[3]=fmaf(a.z,w2.w,acc[3]); acc[3]=fmaf(a.w,w3.w,acc[3]);
}
__global__ __launch_bounds__(256) void k_skip(const float* __restrict__ xf,
                                              const float* __restrict__ Ws,
                                              const float* __restrict__ bs){
    __shared__ __align__(16) float A_s[64][68];
    __shared__ __align__(16) float W_s[64][68];
    int t = threadIdx.x;
    int p0 = blockIdx.x*64;
    float acc[4][4] = {};
    int tr = t>>4, tc = t&15;
    for (int ck = 0; ck < 2; ck++){
        __syncthreads();
        #pragma unroll
        for (int rep = 0; rep < 4; rep++){
            int idx = rep*256 + t;
            int r = idx>>4, kv = idx&15;
            int p = p0 + r;
            float4 v = make_float4(0.f,0.f,0.f,0.f);
            if (p < N_PTS) v = *(const float4*)&xf[p*CI + ck*64 + kv*4];
            *(float4*)&A_s[r][kv*4] = v;
            *(float4*)&W_s[r][kv*4] = *(const float4*)&Ws[(ck*64 + r)*CO + kv*4];
        }
        __syncthreads();
        #pragma unroll
        for (int kk = 0; kk < 64; kk += 4){
            float4 w0 = *(float4*)&W_s[kk+0][tc*4];
            float4 w1 = *(float4*)&W_s[kk+1][tc*4];
            float4 w2 = *(float4*)&W_s[kk+2][tc*4];
            float4 w3 = *(float4*)&W_s[kk+3][tc*4];
            #pragma unroll
            for (int i = 0; i < 4; i++){
                float4 a = *(float4*)&A_s[tr*4+i][kk];
                mma_row(a, w0, w1, w2, w3, acc[i]);
            }
        }
    }
    #pragma unroll
    for (int i = 0; i < 4; i++){
        int p = p0 + tr*4 + i;
        if (p < N_PTS){
            float4 r;
            r.x = acc[i][0] + bs[tc*4+0];
            r.y = acc[i][1] + bs[tc*4+1];
            r.z = acc[i][2] + bs[tc*4+2];
            r.w = acc[i][3] + bs[tc*4+3];
            *(float4*)&g_skip[p*CO + tc*4] = r;
        }
    }
}

// ---------------- MMA on one staged chunk: A[128][32] x B^T[64][32] ----------------
__device__ __forceinline__ void mma_chunk(uint32_t bAh, uint32_t bAl, uint32_t bBh, uint32_t bBl,
                                          int l, int w, float acc[8][4]){
    uint32_t ah[2][4], al[2][4];
    int tile = l>>3, i = l&7;
    int arow = w*16 + (tile&1)*8 + i;
    #pragma unroll
    for (int ks = 0; ks < 2; ks++){
        int acol = ks*16 + (tile>>1)*8;
        ldsm4(ah[ks], bAh + arow*80 + acol*2);
        ldsm4(al[ks], bAl + arow*80 + acol*2);
    }
    int jj = l>>4, sub = (l>>3)&1, bi = l&7;
    #pragma unroll
    for (int jp = 0; jp < 4; jp++){
        #pragma unroll
        for (int ks = 0; ks < 2; ks++){
            int brow = (2*jp + jj)*8 + bi;
            int bcol = ks*16 + sub*8;
            uint32_t bh[4], bl[4];
            ldsm4(bh, bBh + brow*80 + bcol*2);
            ldsm4(bl, bBl + brow*80 + bcol*2);
            mma16816(acc[2*jp],   ah[ks], bh[0], bh[1]);
            mma16816(acc[2*jp],   ah[ks], bl[0], bl[1]);
            mma16816(acc[2*jp],   al[ks], bh[0], bh[1]);
            mma16816(acc[2*jp+1], ah[ks], bh[2], bh[3]);
            mma16816(acc[2*jp+1], ah[ks], bl[2], bl[3]);
            mma16816(acc[2*jp+1], al[ks], bh[2], bh[3]);
        }
    }
}

__device__ __forceinline__ void sts_stage(uint16_t* sAh, uint16_t* sAl, uint16_t* sBh, uint16_t* sBl,
                                          int t, const uint4* av0, const uint4* av1,
                                          uint4 bv0, uint4 bv1){
    #pragma unroll
    for (int it = 0; it < 2; it++){
        int idx = it*256 + t, r = idx>>2, oct = idx&3;
        unpack_store(sAh, sAl, r*5 + oct, av0[it], av1[it]);
    }
    int r = t>>2, oct = t&3;
    unpack_store(sBh, sBl, r*5 + oct, bv0, bv1);
}

// ---------------- conv1: 8 folded parent-neighbors, 32 chunks, pipelined ----------------
__global__ __launch_bounds__(256) void k_conv1_mma(const int* __restrict__ coords,
                                                   const float* __restrict__ b1){
    extern __shared__ __align__(16) char dyn[];
    __shared__ int s_nbr[8][128];
    int t = threadIdx.x, l = t&31, w = t>>5;
    int p0 = blockIdx.x*128;
    int o  = blockIdx.y;
    int dx=(o>>2)&1, dy=(o>>1)&1, dz=o&1;

    if (t < 128){
        int p = p0 + t;
        if (p < N_PTS){
            int x=coords[p*4+1], y=coords[p*4+2], z=coords[p*4+3];
            #pragma unroll
            for (int n = 0; n < 8; n++){
                int ox = dx-1+((n>>2)&1), oy = dy-1+((n>>1)&1), oz = dz-1+(n&1);
                s_nbr[n][t] = g_pgrid[((x+ox+1)*GD + (y+oy+1))*GD + (z+oz+1)];
            }
        } else {
            #pragma unroll
            for (int n = 0; n < 8; n++) s_nbr[n][t] = -1;
        }
    }
    uint16_t* buf[2][4];
    #pragma unroll
    for (int b = 0; b < 2; b++){
        char* base = dyn + b*BUF_BYTES;
        buf[b][0] = (uint16_t*)base;                       // Ah
        buf[b][1] = (uint16_t*)(base + A_HALF*2);          // Al
        buf[b][2] = (uint16_t*)(base + A_HALF*4);          // Bh
        buf[b][3] = (uint16_t*)(base + A_HALF*4 + B_HALF*2);
    }
    uint32_t ba[2][4];
    #pragma unroll
    for (int b = 0; b < 2; b++)
        #pragma unroll
        for (int k = 0; k < 4; k++) ba[b][k] = smem_u32(buf[b][k]);

    float acc[8][4] = {};
    uint4 av0[2], av1[2], bv0, bv1;

    // gather stage 0
    __syncthreads();
    {
        #pragma unroll
        for (int it = 0; it < 2; it++){
            int idx = it*256 + t, r = idx>>2, oct = idx&3;
            int nb = s_nbr[0][r];
            uint4 z = make_uint4(0,0,0,0);
            if (nb >= 0){
                const uint4* src = (const uint4*)&g_h_pk[nb*CI + oct*8];
                av0[it] = src[0]; av1[it] = src[1];
            } else { av0[it]=z; av1[it]=z; }
        }
        int r = t>>2, oct = t&3;
        const uint4* srcB = (const uint4*)&g_weffT_pk[((o*8+0)*CO + r)*CI + oct*8];
        bv0 = srcB[0]; bv1 = srcB[1];
    }
    sts_stage(buf[0][0], buf[0][1], buf[0][2], buf[0][3], t, av0, av1, bv0, bv1);
    __syncthreads();

    for (int st = 0; st < 32; st++){
        int cur = st & 1;
        if (st + 1 < 32){
            int n = (st+1)>>2, q = (st+1)&3;
            #pragma unroll
            for (int it = 0; it < 2; it++){
                int idx = it*256 + t, r = idx>>2, oct = idx&3;
                int nb = s_nbr[n][r];
                uint4 z = make_uint4(0,0,0,0);
                if (nb >= 0){
                    const uint4* src = (const uint4*)&g_h_pk[nb*CI + q*32 + oct*8];
                    av0[it] = src[0]; av1[it] = src[1];
                } else { av0[it]=z; av1[it]=z; }
            }
            int r = t>>2, oct = t&3;
            const uint4* srcB = (const uint4*)&g_weffT_pk[((o*8+n)*CO + r)*CI + q*32 + oct*8];
            bv0 = srcB[0]; bv1 = srcB[1];
        }
        mma_chunk(ba[cur][0], ba[cur][1], ba[cur][2], ba[cur][3], l, w, acc);
        if (st + 1 < 32){
            int nxt = cur ^ 1;
            sts_stage(buf[nxt][0], buf[nxt][1], buf[nxt][2], buf[nxt][3], t, av0, av1, bv0, bv1);
        }
        __syncthreads();
    }

    int r0 = w*16 + (l>>2);
    #pragma unroll
    for (int j = 0; j < 8; j++){
        int col = j*8 + (l&3)*2;
        int p_0 = p0 + r0;
        if (p_0 < N_PTS){
            float2 v; v.x = acc[j][0] + b1[col]; v.y = acc[j][1] + b1[col+1];
            *(float2*)&g_mid[((size_t)p_0*8 + o)*CO + col] = v;
        }
        int p_1 = p0 + r0 + 8;
        if (p_1 < N_PTS){
            float2 v; v.x = acc[j][2] + b1[col]; v.y = acc[j][3] + b1[col+1];
            *(float2*)&g_mid[((size_t)p_1*8 + o)*CO + col] = v;
        }
    }
}

__global__ void k_stats2(){
    __shared__ float ss[256], ss2[256];
    int t = threadIdx.x; int c = t&63; int lane = t>>6;
    float s=0.f, s2=0.f;
    for (int r = blockIdx.x*4 + lane; r < M_PTS; r += gridDim.x*4){
        float v = g_mid[r*CO + c]; s += v; s2 += v*v;
    }
    ss[t]=s; ss2[t]=s2; __syncthreads();
    if (t < 64){
        float a = ss[t]+ss[t+64]+ss[t+128]+ss[t+192];
        float b = ss2[t]+ss2[t+64]+ss2[t+128]+ss2[t+192];
        atomicAdd(&g_sum2[c], a); atomicAdd(&g_sq2[c], b);
    }
}
__global__ void k_fin2(){
    int g = threadIdx.x;
    if (g < 32){
        float s  = g_sum2[2*g] + g_sum2[2*g+1];
        float s2 = g_sq2[2*g]  + g_sq2[2*g+1];
        float inv = 1.f/(float)(M_PTS*2);
        float mu = s*inv, var = s2*inv - mu*mu;
        g_mu2[g] = mu; g_rs2[g] = rsqrtf(var + 1e-5f);
    }
}
__global__ void k_act(const float* __restrict__ gma, const float* __restrict__ bta){
    int i = blockIdx.x*256 + threadIdx.x;
    int c = i & 63; int g = c >> 1;
    float v = (g_mid[i] - g_mu2[g])*g_rs2[g]*gma[c] + bta[c];
    v = v / (1.f + expf(-v));
    g_act_pk[i] = pack_hl(v);
}

// ---------------- conv2: 27 taps x 2 K-chunks = 54 stages, pipelined ----------------
__global__ __launch_bounds__(256) void k_conv2_mma(const int* __restrict__ coords,
                                                   const float* __restrict__ b2,
                                                   float* __restrict__ out){
    extern __shared__ __align__(16) char dyn[];
    __shared__ int s_nbr[27][128];
    int t = threadIdx.x, l = t&31, w = t>>5;
    int m0 = blockIdx.x*128;

    if (t < 128){
        int m = m0 + t, p = m>>3, oo = m&7;
        int cx = 2*coords[p*4+1] + ((oo>>2)&1);
        int cy = 2*coords[p*4+2] + ((oo>>1)&1);
        int cz = 2*coords[p*4+3] + (oo&1);
        #pragma unroll
        for (int tap = 0; tap < 27; tap++){
            int ax = cx + tap/9 - 1;
            int ay = cy + (tap/3)%3 - 1;
            int az = cz + tap%3 - 1;
            int q = g_pgrid[(((ax>>1)+1)*GD + ((ay>>1)+1))*GD + ((az>>1)+1)];
            s_nbr[tap][t] = (q >= 0) ? (q*8 + ((ax&1)<<2) + ((ay&1)<<1) + (az&1)) : -1;
        }
    }
    uint16_t* buf[2][4];
    #pragma unroll
    for (int b = 0; b < 2; b++){
        char* base = dyn + b*BUF_BYTES;
        buf[b][0] = (uint16_t*)base;
        buf[b][1] = (uint16_t*)(base + A_HALF*2);
        buf[b][2] = (uint16_t*)(base + A_HALF*4);
        buf[b][3] = (uint16_t*)(base + A_HALF*4 + B_HALF*2);
    }
    uint32_t ba[2][4];
    #pragma unroll
    for (int b = 0; b < 2; b++)
        #pragma unroll
        for (int k = 0; k < 4; k++) ba[b][k] = smem_u32(buf[b][k]);

    float acc[8][4] = {};
    uint4 av0[2], av1[2], bv0, bv1;

    __syncthreads();
    {
        #pragma unroll
        for (int it = 0; it < 2; it++){
            int idx = it*256 + t, r = idx>>2, oct = idx&3;
            int nb = s_nbr[0][r];
            uint4 z = make_uint4(0,0,0,0);
            if (nb >= 0){
                const uint4* src = (const uint4*)&g_act_pk[nb*CO + oct*8];
                av0[it] = src[0]; av1[it] = src[1];
            } else { av0[it]=z; av1[it]=z; }
        }
        int r = t>>2, oct = t&3;
        const uint4* srcB = (const uint4*)&g_w2t_pk[(0*CO + r)*CO + oct*8];
        bv0 = srcB[0]; bv1 = srcB[1];
    }
    sts_stage(buf[0][0], buf[0][1], buf[0][2], buf[0][3], t, av0, av1, bv0, bv1);
    __syncthreads();

    for (int st = 0; st < 54; st++){
        int cur = st & 1;
        if (st + 1 < 54){
            int tap = (st+1)>>1, ck = (st+1)&1;
            #pragma unroll
            for (int it = 0; it < 2; it++){
                int idx = it*256 + t, r = idx>>2, oct = idx&3;
                int nb = s_nbr[tap][r];
                uint4 z = make_uint4(0,0,0,0);
                if (nb >= 0){
                    const uint4* src = (const uint4*)&g_act_pk[nb*CO + ck*32 + oct*8];
                    av0[it] = src[0]; av1[it] = src[1];
                } else { av0[it]=z; av1[it]=z; }
            }
            int r = t>>2, oct = t&3;
            const uint4* srcB = (const uint4*)&g_w2t_pk[(tap*CO + r)*CO + ck*32 + oct*8];
            bv0 = srcB[0]; bv1 = srcB[1];
        }
        mma_chunk(ba[cur][0], ba[cur][1], ba[cur][2], ba[cur][3], l, w, acc);
        if (st + 1 < 54){
            int nxt = cur ^ 1;
            sts_stage(buf[nxt][0], buf[nxt][1], buf[nxt][2], buf[nxt][3], t, av0, av1, bv0, bv1);
        }
        __syncthreads();
    }

    int r0 = w*16 + (l>>2);
    #pragma unroll
    for (int j = 0; j < 8; j++){
        int col = j*8 + (l&3)*2;
        {
            int m = m0 + r0, p = m>>3;
            float2 v;
            v.x = acc[j][0] + b2[col]   + g_skip[p*CO + col];
            v.y = acc[j][1] + b2[col+1] + g_skip[p*CO + col+1];
            *(float2*)&out[(size_t)m*CO + col] = v;
        }
        {
            int m = m0 + r0 + 8, p = m>>3;
            float2 v;
            v.x = acc[j][2] + b2[col]   + g_skip[p*CO + col];
            v.y = acc[j][3] + b2[col+1] + g_skip[p*CO + col+1];
            *(float2*)&out[(size_t)m*CO + col] = v;
        }
    }
}

// ---------------- launch ----------------
extern "C" void kernel_launch(void* const* d_in, const int* in_sizes, int n_in,
                              void* d_out, int out_size){
    const float* xf    = (const float*)d_in[0];
    const int*   coords= (const int*)  d_in[1];
    const float* gn1g  = (const float*)d_in[2];
    const float* gn1b  = (const float*)d_in[3];
    const float* W1    = (const float*)d_in[4];
    const float* b1    = (const float*)d_in[5];
    const float* gn2g  = (const float*)d_in[6];
    const float* gn2b  = (const float*)d_in[7];
    const float* W2    = (const float*)d_in[8];
    const float* b2    = (const float*)d_in[9];
    const float* Ws    = (const float*)d_in[10];
    const float* bs    = (const float*)d_in[11];
    float* out = (float*)d_out;

    static int attr_done = 0;
    if (!attr_done){
        cudaFuncSetAttribute(k_conv1_mma, cudaFuncAttributeMaxDynamicSharedMemorySize, SMEM_DYN);
        cudaFuncSetAttribute(k_conv2_mma, cudaFuncAttributeMaxDynamicSharedMemorySize, SMEM_DYN);
        attr_done = 1;
    }

    k_init<<<(GSZ+255)/256, 256>>>();
    k_scatter<<<(N_PTS+255)/256, 256>>>(coords);
    k_stats1<<<160, 128>>>(xf);
    k_fin1<<<1, 32>>>();
    k_h<<<N_PTS*CI/256, 256>>>(xf, gn1g, gn1b);
    k_weffT<<<8*8*CI*CO/256, 256>>>(W1);
    k_w2t<<<(27*CO*CO+255)/256, 256>>>(W2);
    k_skip<<<(N_PTS+63)/64, 256>>>(xf, Ws, bs);
    k_conv1_mma<<<dim3((N_PTS+127)/128, 8), 256, SMEM_DYN>>>(coords, b1);
    k_stats2<<<400, 256>>>();
    k_fin2<<<1, 32>>>();
    k_act<<<M_PTS*CO/256, 256>>>(gn2g, gn2b);
    k_conv2_mma<<<M_PTS/128, 256, SMEM_DYN>>>(coords, b2, out);
}

// round 9
// speedup vs baseline: 2.0055x; 2.0055x over previous
#include <cuda_runtime.h>
#include <cuda_fp16.h>
#include <cstdint>
#include <math.h>

#define N_PTS 20000
#define M_PTS 160000
#define CI 128
#define CO 64
#define GD 34
#define GSZ (GD*GD*GD)

// stage: A 128x64 fp16 (row pad 72), B 64x64 fp16 (row pad 72)
#define A_PAD 72
#define SMEM_A_BYTES (128*A_PAD*2)     // 18432
#define SMEM_B_BYTES (64*A_PAD*2)      // 9216
#define SMEM_DYN (SMEM_A_BYTES + SMEM_B_BYTES)   // 27648 < 48KB default

// ---------------- device scratch ----------------
__device__ int    g_pgrid[GSZ];
__device__ __align__(16) __half g_h_h[N_PTS*CI];       // silu(gn1(x)) fp16
__device__ float  g_skip[N_PTS*CO];
__device__ float  g_mid[M_PTS*CO];                     // conv1 out fp32
__device__ __align__(16) __half g_act_h[M_PTS*CO];     // silu(gn2(mid)) fp16
__device__ __align__(16) __half g_weffT_h[8*8*CO*CI];  // [o][n][cout][cin]
__device__ __align__(16) __half g_w2t_h[27*CO*CO];     // [tap][cout][cin]
__device__ float g_sum1[CI], g_sq1[CI], g_mu1[32], g_rs1[32];
__device__ float g_sum2[CO], g_sq2[CO], g_mu2[32], g_rs2[32];

// ---------------- helpers ----------------
__device__ __forceinline__ uint32_t smem_u32(const void* p){
    uint32_t a;
    asm("{ .reg .u64 t; cvta.to.shared.u64 t, %1; cvt.u32.u64 %0, t; }" : "=r"(a) : "l"(p));
    return a;
}
__device__ __forceinline__ void ldsm4(uint32_t* r, uint32_t addr){
    asm volatile("ldmatrix.sync.aligned.m8n8.x4.shared.b16 {%0,%1,%2,%3}, [%4];"
        : "=r"(r[0]),"=r"(r[1]),"=r"(r[2]),"=r"(r[3]) : "r"(addr));
}
__device__ __forceinline__ void mma16816(float* d, const uint32_t* a, uint32_t b0, uint32_t b1){
    asm volatile("mma.sync.aligned.m16n8k16.row.col.f32.f16.f16.f32 "
        "{%0,%1,%2,%3}, {%4,%5,%6,%7}, {%8,%9}, {%0,%1,%2,%3};"
        : "+f"(d[0]),"+f"(d[1]),"+f"(d[2]),"+f"(d[3])
        : "r"(a[0]),"r"(a[1]),"r"(a[2]),"r"(a[3]), "r"(b0),"r"(b1));
}

// ---------------- small kernels ----------------
__global__ void k_init(){
    int i = blockIdx.x*256 + threadIdx.x;
    if (i < GSZ) g_pgrid[i] = -1;
    if (i < CI){ g_sum1[i]=0.f; g_sq1[i]=0.f; }
    if (i < CO){ g_sum2[i]=0.f; g_sq2[i]=0.f; }
}
__global__ void k_scatter(const int* __restrict__ coords){
    int p = blockIdx.x*256 + threadIdx.x;
    if (p < N_PTS){
        int x=coords[p*4+1], y=coords[p*4+2], z=coords[p*4+3];
        g_pgrid[((x+1)*GD + (y+1))*GD + (z+1)] = p;
    }
}
__global__ void k_stats1(const float* __restrict__ xf){
    int c = threadIdx.x;
    float s=0.f, s2=0.f;
    for (int r = blockIdx.x; r < N_PTS; r += gridDim.x){
        float v = xf[r*CI + c]; s += v; s2 += v*v;
    }
    atomicAdd(&g_sum1[c], s); atomicAdd(&g_sq1[c], s2);
}
__global__ void k_fin1(){
    int g = threadIdx.x;
    if (g < 32){
        float s=0.f, s2=0.f;
        for (int j=0;j<4;j++){ s += g_sum1[g*4+j]; s2 += g_sq1[g*4+j]; }
        float inv = 1.f/(float)(N_PTS*4);
        float mu = s*inv, var = s2*inv - mu*mu;
        g_mu1[g] = mu; g_rs1[g] = rsqrtf(var + 1e-5f);
    }
}
__global__ void k_h(const float* __restrict__ xf,
                    const float* __restrict__ gma, const float* __restrict__ bta){
    int i = blockIdx.x*256 + threadIdx.x;
    int c = i & (CI-1); int g = c >> 2;
    float v = (xf[i] - g_mu1[g])*g_rs1[g]*gma[c] + bta[c];
    v = v / (1.f + expf(-v));
    g_h_h[i] = __float2half(v);
}
__global__ void k_weffT(const float* __restrict__ W1){
    int idx = blockIdx.x*256 + threadIdx.x;   // 8*8*128*64
    int cout = idx & 63, cin = (idx>>6)&127, n = (idx>>13)&7, o = idx>>16;
    int d0=(o>>2)&1, d1=(o>>1)&1, d2=o&1;
    int n0=(n>>2)&1, n1=(n>>1)&1, n2=n&1;
    float s = 0.f;
    for (int i=0;i<3;i++){
        int t0=d0+i-1; int p0=(t0>=2)?1:((t0>=0)?0:-1);
        if (p0 - d0 + 1 != n0) continue;
        for (int j=0;j<3;j++){
            int t1=d1+j-1; int p1=(t1>=2)?1:((t1>=0)?0:-1);
            if (p1 - d1 + 1 != n1) continue;
            for (int k=0;k<3;k++){
                int t2=d2+k-1; int p2=(t2>=2)?1:((t2>=0)?0:-1);
                if (p2 - d2 + 1 != n2) continue;
                s += W1[(((i*3+j)*3+k)*CI + cin)*CO + cout];
            }
        }
    }
    g_weffT_h[((o*8+n)*CO + cout)*CI + cin] = __float2half(s);
}
__global__ void k_w2t(const float* __restrict__ W2){
    int idx = blockIdx.x*256 + threadIdx.x;   // 27*64*64
    if (idx >= 27*CO*CO) return;
    int cout = idx & 63, cin = (idx>>6)&63, tap = idx>>12;
    g_w2t_h[(tap*CO + cout)*CO + cin] = __float2half(W2[(tap*CO + cin)*CO + cout]);
}

// ---------------- skip GEMM (scalar fp32, tiny, exact) ----------------
__device__ __forceinline__ void mma_row(float4 a, float4 w0, float4 w1, float4 w2, float4 w3,
                                        float acc[4]){
    acc[0]=fmaf(a.x,w0.x,acc[0]); acc[0]=fmaf(a.y,w1.x,acc[0]); acc[0]=fmaf(a.z,w2.x,acc[0]); acc[0]=fmaf(a.w,w3.x,acc[0]);
    acc[1]=fmaf(a.x,w0.y,acc[1]); acc[1]=fmaf(a.y,w1.y,acc[1]); acc[1]=fmaf(a.z,w2.y,acc[1]); acc[1]=fmaf(a.w,w3.y,acc[1]);
    acc[2]=fmaf(a.x,w0.z,acc[2]); acc[2]=fmaf(a.y,w1.z,acc[2]); acc[2]=fmaf(a.z,w2.z,acc[2]); acc[2]=fmaf(a.w,w3.z,acc[2]);
    acc[3]=fmaf(a.x,w0.w,acc[3]); acc[3]=fmaf(a.y,w1.w,acc[3]); acc[3]=fmaf(a.z,w2.w,acc[3]); acc[3]=fmaf(a.w,w3.w,acc[3]);
}
__global__ __launch_bounds__(256) void k_skip(const float* __restrict__ xf,
                                              const float* __restrict__ Ws,
                                              const float* __restrict__ bs){
    __shared__ __align__(16) float A_s[64][68];
    __shared__ __align__(16) float W_s[64][68];
    int t = threadIdx.x;
    int p0 = blockIdx.x*64;
    float acc[4][4] = {};
    int tr = t>>4, tc = t&15;
    for (int ck = 0; ck < 2; ck++){
        __syncthreads();
        #pragma unroll
        for (int rep = 0; rep < 4; rep++){
            int idx = rep*256 + t;
            int r = idx>>4, kv = idx&15;
            int p = p0 + r;
            float4 v = make_float4(0.f,0.f,0.f,0.f);
            if (p < N_PTS) v = *(const float4*)&xf[p*CI + ck*64 + kv*4];
            *(float4*)&A_s[r][kv*4] = v;
            *(float4*)&W_s[r][kv*4] = *(const float4*)&Ws[(ck*64 + r)*CO + kv*4];
        }
        __syncthreads();
        #pragma unroll
        for (int kk = 0; kk < 64; kk += 4){
            float4 w0 = *(float4*)&W_s[kk+0][tc*4];
            float4 w1 = *(float4*)&W_s[kk+1][tc*4];
            float4 w2 = *(float4*)&W_s[kk+2][tc*4];
            float4 w3 = *(float4*)&W_s[kk+3][tc*4];
            #pragma unroll
            for (int i = 0; i < 4; i++){
                float4 a = *(float4*)&A_s[tr*4+i][kk];
                mma_row(a, w0, w1, w2, w3, acc[i]);
            }
        }
    }
    #pragma unroll
    for (int i = 0; i < 4; i++){
        int p = p0 + tr*4 + i;
        if (p < N_PTS){
            float4 r;
            r.x = acc[i][0] + bs[tc*4+0];
            r.y = acc[i][1] + bs[tc*4+1];
            r.z = acc[i][2] + bs[tc*4+2];
            r.w = acc[i][3] + bs[tc*4+3];
            *(float4*)&g_skip[p*CO + tc*4] = r;
        }
    }
}

// ---------------- MMA on one staged chunk: A[128][64] x B^T[64][64] fp16 ----------------
__device__ __forceinline__ void mma_chunk64(uint32_t bA, uint32_t bB, int l, int w,
                                            float acc[8][4]){
    uint32_t a[4][4];
    int tile = l>>3, i = l&7;
    int arow = w*16 + (tile&1)*8 + i;
    #pragma unroll
    for (int ks = 0; ks < 4; ks++){
        int acol = ks*16 + (tile>>1)*8;
        ldsm4(a[ks], bA + arow*(A_PAD*2) + acol*2);
    }
    int jj = l>>4, sub = (l>>3)&1, bi = l&7;
    #pragma unroll
    for (int jp = 0; jp < 4; jp++){
        #pragma unroll
        for (int ks = 0; ks < 4; ks++){
            int brow = (2*jp + jj)*8 + bi;
            int bcol = ks*16 + sub*8;
            uint32_t b[4];
            ldsm4(b, bB + brow*(A_PAD*2) + bcol*2);
            mma16816(acc[2*jp],   a[ks], b[0], b[1]);
            mma16816(acc[2*jp+1], a[ks], b[2], b[3]);
        }
    }
}

// ---------------- conv1: 8 folded neighbors x 2 K-chunks = 16 stages ----------------
__global__ __launch_bounds__(256) void k_conv1_mma(const int* __restrict__ coords,
                                                   const float* __restrict__ b1){
    extern __shared__ __align__(16) char dyn[];
    __half* sA = (__half*)dyn;
    __half* sB = (__half*)(dyn + SMEM_A_BYTES);
    __shared__ int s_nbr[8][128];
    int t = threadIdx.x, l = t&31, w = t>>5;
    int p0 = blockIdx.x*128;
    int o  = blockIdx.y;
    int dx=(o>>2)&1, dy=(o>>1)&1, dz=o&1;

    if (t < 128){
        int p = p0 + t;
        if (p < N_PTS){
            int x=coords[p*4+1], y=coords[p*4+2], z=coords[p*4+3];
            #pragma unroll
            for (int n = 0; n < 8; n++){
                int ox = dx-1+((n>>2)&1), oy = dy-1+((n>>1)&1), oz = dz-1+(n&1);
                s_nbr[n][t] = g_pgrid[((x+ox+1)*GD + (y+oy+1))*GD + (z+oz+1)];
            }
        } else {
            #pragma unroll
            for (int n = 0; n < 8; n++) s_nbr[n][t] = -1;
        }
    }
    uint32_t bA = smem_u32(sA), bB = smem_u32(sB);
    float acc[8][4] = {};

    for (int st = 0; st < 16; st++){
        int n = st>>1, ck = st&1;
        __syncthreads();
        #pragma unroll
        for (int it = 0; it < 4; it++){
            int lin = it*256 + t;
            int r = lin>>3, c8 = lin&7;
            int nb = s_nbr[n][r];
            uint4 v = make_uint4(0,0,0,0);
            if (nb >= 0) v = *(const uint4*)&g_h_h[nb*CI + ck*64 + c8*8];
            *(uint4*)&sA[r*A_PAD + c8*8] = v;
        }
        #pragma unroll
        for (int it = 0; it < 2; it++){
            int lin = it*256 + t;
            int r = lin>>3, c8 = lin&7;
            *(uint4*)&sB[r*A_PAD + c8*8] =
                *(const uint4*)&g_weffT_h[((o*8+n)*CO + r)*CI + ck*64 + c8*8];
        }
        __syncthreads();
        mma_chunk64(bA, bB, l, w, acc);
    }

    int r0 = w*16 + (l>>2);
    #pragma unroll
    for (int j = 0; j < 8; j++){
        int col = j*8 + (l&3)*2;
        int p_0 = p0 + r0;
        if (p_0 < N_PTS){
            float2 v; v.x = acc[j][0] + b1[col]; v.y = acc[j][1] + b1[col+1];
            *(float2*)&g_mid[((size_t)p_0*8 + o)*CO + col] = v;
        }
        int p_1 = p0 + r0 + 8;
        if (p_1 < N_PTS){
            float2 v; v.x = acc[j][2] + b1[col]; v.y = acc[j][3] + b1[col+1];
            *(float2*)&g_mid[((size_t)p_1*8 + o)*CO + col] = v;
        }
    }
}

__global__ void k_stats2(){
    __shared__ float ss[256], ss2[256];
    int t = threadIdx.x; int c = t&63; int lane = t>>6;
    float s=0.f, s2=0.f;
    for (int r = blockIdx.x*4 + lane; r < M_PTS; r += gridDim.x*4){
        float v = g_mid[r*CO + c]; s += v; s2 += v*v;
    }
    ss[t]=s; ss2[t]=s2; __syncthreads();
    if (t < 64){
        float a = ss[t]+ss[t+64]+ss[t+128]+ss[t+192];
        float b = ss2[t]+ss2[t+64]+ss2[t+128]+ss2[t+192];
        atomicAdd(&g_sum2[c], a); atomicAdd(&g_sq2[c], b);
    }
}
__global__ void k_fin2(){
    int g = threadIdx.x;
    if (g < 32){
        float s  = g_sum2[2*g] + g_sum2[2*g+1];
        float s2 = g_sq2[2*g]  + g_sq2[2*g+1];
        float inv = 1.f/(float)(M_PTS*2);
        float mu = s*inv, var = s2*inv - mu*mu;
        g_mu2[g] = mu; g_rs2[g] = rsqrtf(var + 1e-5f);
    }
}
__global__ void k_act(const float* __restrict__ gma, const float* __restrict__ bta){
    int i = blockIdx.x*256 + threadIdx.x;
    int c = i & 63; int g = c >> 1;
    float v = (g_mid[i] - g_mu2[g])*g_rs2[g]*gma[c] + bta[c];
    v = v / (1.f + expf(-v));
    g_act_h[i] = __float2half(v);
}

// ---------------- conv2: 27 taps (K=64 each), + bias + skip ----------------
__global__ __launch_bounds__(256) void k_conv2_mma(const int* __restrict__ coords,
                                                   const float* __restrict__ b2,
                                                   float* __restrict__ out){
    extern __shared__ __align__(16) char dyn[];
    __half* sA = (__half*)dyn;
    __half* sB = (__half*)(dyn + SMEM_A_BYTES);
    __shared__ int s_nbr[27][128];
    int t = threadIdx.x, l = t&31, w = t>>5;
    int m0 = blockIdx.x*128;     // M_PTS/128 = 1250 exact

    if (t < 128){
        int m = m0 + t, p = m>>3, oo = m&7;
        int cx = 2*coords[p*4+1] + ((oo>>2)&1);
        int cy = 2*coords[p*4+2] + ((oo>>1)&1);
        int cz = 2*coords[p*4+3] + (oo&1);
        #pragma unroll
        for (int tap = 0; tap < 27; tap++){
            int ax = cx + tap/9 - 1;
            int ay = cy + (tap/3)%3 - 1;
            int az = cz + tap%3 - 1;
            int q = g_pgrid[(((ax>>1)+1)*GD + ((ay>>1)+1))*GD + ((az>>1)+1)];
            s_nbr[tap][t] = (q >= 0) ? (q*8 + ((ax&1)<<2) + ((ay&1)<<1) + (az&1)) : -1;
        }
    }
    uint32_t bA = smem_u32(sA), bB = smem_u32(sB);
    float acc[8][4] = {};

    for (int tap = 0; tap < 27; tap++){
        __syncthreads();
        #pragma unroll
        for (int it = 0; it < 4; it++){
            int lin = it*256 + t;
            int r = lin>>3, c8 = lin&7;
            int nb = s_nbr[tap][r];
            uint4 v = make_uint4(0,0,0,0);
            if (nb >= 0) v = *(const uint4*)&g_act_h[nb*CO + c8*8];
            *(uint4*)&sA[r*A_PAD + c8*8] = v;
        }
        #pragma unroll
        for (int it = 0; it < 2; it++){
            int lin = it*256 + t;
            int r = lin>>3, c8 = lin&7;
            *(uint4*)&sB[r*A_PAD + c8*8] =
                *(const uint4*)&g_w2t_h[(tap*CO + r)*CO + c8*8];
        }
        __syncthreads();
        mma_chunk64(bA, bB, l, w, acc);
    }

    int r0 = w*16 + (l>>2);
    #pragma unroll
    for (int j = 0; j < 8; j++){
        int col = j*8 + (l&3)*2;
        {
            int m = m0 + r0, p = m>>3;
            float2 v;
            v.x = acc[j][0] + b2[col]   + g_skip[p*CO + col];
            v.y = acc[j][1] + b2[col+1] + g_skip[p*CO + col+1];
            *(float2*)&out[(size_t)m*CO + col] = v;
        }
        {
            int m = m0 + r0 + 8, p = m>>3;
            float2 v;
            v.x = acc[j][2] + b2[col]   + g_skip[p*CO + col];
            v.y = acc[j][3] + b2[col+1] + g_skip[p*CO + col+1];
            *(float2*)&out[(size_t)m*CO + col] = v;
        }
    }
}

// ---------------- launch ----------------
extern "C" void kernel_launch(void* const* d_in, const int* in_sizes, int n_in,
                              void* d_out, int out_size){
    const float* xf    = (const float*)d_in[0];
    const int*   coords= (const int*)  d_in[1];
    const float* gn1g  = (const float*)d_in[2];
    const float* gn1b  = (const float*)d_in[3];
    const float* W1    = (const float*)d_in[4];
    const float* b1    = (const float*)d_in[5];
    const float* gn2g  = (const float*)d_in[6];
    const float* gn2b  = (const float*)d_in[7];
    const float* W2    = (const float*)d_in[8];
    const float* b2    = (const float*)d_in[9];
    const float* Ws    = (const float*)d_in[10];
    const float* bs    = (const float*)d_in[11];
    float* out = (float*)d_out;

    k_init<<<(GSZ+255)/256, 256>>>();
    k_scatter<<<(N_PTS+255)/256, 256>>>(coords);
    k_stats1<<<160, 128>>>(xf);
    k_fin1<<<1, 32>>>();
    k_h<<<N_PTS*CI/256, 256>>>(xf, gn1g, gn1b);
    k_weffT<<<8*8*CI*CO/256, 256>>>(W1);
    k_w2t<<<(27*CO*CO+255)/256, 256>>>(W2);
    k_skip<<<(N_PTS+63)/64, 256>>>(xf, Ws, bs);
    k_conv1_mma<<<dim3((N_PTS+127)/128, 8), 256, SMEM_DYN>>>(coords, b1);
    k_stats2<<<400, 256>>>();
    k_fin2<<<1, 32>>>();
    k_act<<<M_PTS*CO/256, 256>>>(gn2g, gn2b);
    k_conv2_mma<<<M_PTS/128, 256, SMEM_DYN>>>(coords, b2, out);
}

// round 10
// speedup vs baseline: 2.0983x; 1.0463x over previous
#include <cuda_runtime.h>
#include <cuda_fp16.h>
#include <cstdint>
#include <math.h>

#define N_PTS 20000
#define M_PTS 160000
#define CI 128
#define CO 64
#define GD 34
#define GSZ (GD*GD*GD)

// stage: A 128x64 fp16 (row pad 72 halves = 144B), B 64x64 fp16 (same pad)
#define A_PAD 72
#define SMEM_A_BYTES (128*A_PAD*2)     // 18432
#define SMEM_B_BYTES (64*A_PAD*2)      // 9216
#define STG_BYTES (SMEM_A_BYTES + SMEM_B_BYTES)   // 27648
#define SMEM_DYN (3*STG_BYTES)                     // 82944

// ---------------- device scratch ----------------
__device__ int    g_pgrid[GSZ];
__device__ __align__(16) __half g_h_h[N_PTS*CI];       // silu(gn1(x)) fp16
__device__ float  g_skip[N_PTS*CO];
__device__ float  g_mid[M_PTS*CO];                     // conv1 out fp32
__device__ __align__(16) __half g_act_h[M_PTS*CO];     // silu(gn2(mid)) fp16
__device__ __align__(16) __half g_weffT_h[8*8*CO*CI];  // [o][n][cout][cin]
__device__ __align__(16) __half g_w2t_h[27*CO*CO];     // [tap][cout][cin]
__device__ float g_sum1[CI], g_sq1[CI], g_mu1[32], g_rs1[32];
__device__ float g_sum2[CO], g_sq2[CO], g_mu2[32], g_rs2[32];

// ---------------- helpers ----------------
__device__ __forceinline__ uint32_t smem_u32(const void* p){
    uint32_t a;
    asm("{ .reg .u64 t; cvta.to.shared.u64 t, %1; cvt.u32.u64 %0, t; }" : "=r"(a) : "l"(p));
    return a;
}
__device__ __forceinline__ void cp_async16(uint32_t dst, const void* src, int src_size){
    asm volatile("cp.async.ca.shared.global [%0], [%1], 16, %2;"
                 :: "r"(dst), "l"(src), "r"(src_size) : "memory");
}
#define CP_COMMIT() asm volatile("cp.async.commit_group;" ::: "memory")
#define CP_WAIT(n)  asm volatile("cp.async.wait_group %0;" :: "n"(n) : "memory")

__device__ __forceinline__ void ldsm4(uint32_t* r, uint32_t addr){
    asm volatile("ldmatrix.sync.aligned.m8n8.x4.shared.b16 {%0,%1,%2,%3}, [%4];"
        : "=r"(r[0]),"=r"(r[1]),"=r"(r[2]),"=r"(r[3]) : "r"(addr));
}
__device__ __forceinline__ void mma16816(float* d, const uint32_t* a, uint32_t b0, uint32_t b1){
    asm volatile("mma.sync.aligned.m16n8k16.row.col.f32.f16.f16.f32 "
        "{%0,%1,%2,%3}, {%4,%5,%6,%7}, {%8,%9}, {%0,%1,%2,%3};"
        : "+f"(d[0]),"+f"(d[1]),"+f"(d[2]),"+f"(d[3])
        : "r"(a[0]),"r"(a[1]),"r"(a[2]),"r"(a[3]), "r"(b0),"r"(b1));
}

// ---------------- small kernels ----------------
__global__ void k_init(){
    int i = blockIdx.x*256 + threadIdx.x;
    if (i < GSZ) g_pgrid[i] = -1;
    if (i < CI){ g_sum1[i]=0.f; g_sq1[i]=0.f; }
    if (i < CO){ g_sum2[i]=0.f; g_sq2[i]=0.f; }
}
__global__ void k_scatter(const int* __restrict__ coords){
    int p = blockIdx.x*256 + threadIdx.x;
    if (p < N_PTS){
        int x=coords[p*4+1], y=coords[p*4+2], z=coords[p*4+3];
        g_pgrid[((x+1)*GD + (y+1))*GD + (z+1)] = p;
    }
}
__global__ void k_stats1(const float* __restrict__ xf){
    int c = threadIdx.x;
    float s=0.f, s2=0.f;
    for (int r = blockIdx.x; r < N_PTS; r += gridDim.x){
        float v = xf[r*CI + c]; s += v; s2 += v*v;
    }
    atomicAdd(&g_sum1[c], s); atomicAdd(&g_sq1[c], s2);
}
__global__ void k_fin1(){
    int g = threadIdx.x;
    if (g < 32){
        float s=0.f, s2=0.f;
        for (int j=0;j<4;j++){ s += g_sum1[g*4+j]; s2 += g_sq1[g*4+j]; }
        float inv = 1.f/(float)(N_PTS*4);
        float mu = s*inv, var = s2*inv - mu*mu;
        g_mu1[g] = mu; g_rs1[g] = rsqrtf(var + 1e-5f);
    }
}
__global__ void k_h(const float* __restrict__ xf,
                    const float* __restrict__ gma, const float* __restrict__ bta){
    int i = blockIdx.x*256 + threadIdx.x;
    int c = i & (CI-1); int g = c >> 2;
    float v = (xf[i] - g_mu1[g])*g_rs1[g]*gma[c] + bta[c];
    v = v / (1.f + expf(-v));
    g_h_h[i] = __float2half(v);
}
__global__ void k_weffT(const float* __restrict__ W1){
    int idx = blockIdx.x*256 + threadIdx.x;   // 8*8*128*64
    int cout = idx & 63, cin = (idx>>6)&127, n = (idx>>13)&7, o = idx>>16;
    int d0=(o>>2)&1, d1=(o>>1)&1, d2=o&1;
    int n0=(n>>2)&1, n1=(n>>1)&1, n2=n&1;
    float s = 0.f;
    for (int i=0;i<3;i++){
        int t0=d0+i-1; int p0=(t0>=2)?1:((t0>=0)?0:-1);
        if (p0 - d0 + 1 != n0) continue;
        for (int j=0;j<3;j++){
            int t1=d1+j-1; int p1=(t1>=2)?1:((t1>=0)?0:-1);
            if (p1 - d1 + 1 != n1) continue;
            for (int k=0;k<3;k++){
                int t2=d2+k-1; int p2=(t2>=2)?1:((t2>=0)?0:-1);
                if (p2 - d2 + 1 != n2) continue;
                s += W1[(((i*3+j)*3+k)*CI + cin)*CO + cout];
            }
        }
    }
    g_weffT_h[((o*8+n)*CO + cout)*CI + cin] = __float2half(s);
}
__global__ void k_w2t(const float* __restrict__ W2){
    int idx = blockIdx.x*256 + threadIdx.x;   // 27*64*64
    if (idx >= 27*CO*CO) return;
    int cout = idx & 63, cin = (idx>>6)&63, tap = idx>>12;
    g_w2t_h[(tap*CO + cout)*CO + cin] = __float2half(W2[(tap*CO + cin)*CO + cout]);
}

// ---------------- skip GEMM (scalar fp32, tiny, exact) ----------------
__device__ __forceinline__ void mma_row(float4 a, float4 w0, float4 w1, float4 w2, float4 w3,
                                        float acc[4]){
    acc[0]=fmaf(a.x,w0.x,acc[0]); acc[0]=fmaf(a.y,w1.x,acc[0]); acc[0]=fmaf(a.z,w2.x,acc[0]); acc[0]=fmaf(a.w,w3.x,acc[0]);
    acc[1]=fmaf(a.x,w0.y,acc[1]); acc[1]=fmaf(a.y,w1.y,acc[1]); acc[1]=fmaf(a.z,w2.y,acc[1]); acc[1]=fmaf(a.w,w3.y,acc[1]);
    acc[2]=fmaf(a.x,w0.z,acc[2]); acc[2]=fmaf(a.y,w1.z,acc[2]); acc[2]=fmaf(a.z,w2.z,acc[2]); acc[2]=fmaf(a.w,w3.z,acc[2]);
    acc[3]=fmaf(a.x,w0.w,acc[3]); acc[3]=fmaf(a.y,w1.w,acc[3]); acc[3]=fmaf(a.z,w2.w,acc[3]); acc[3]=fmaf(a.w,w3.w,acc[3]);
}
__global__ __launch_bounds__(256) void k_skip(const float* __restrict__ xf,
                                              const float* __restrict__ Ws,
                                              const float* __restrict__ bs){
    __shared__ __align__(16) float A_s[64][68];
    __shared__ __align__(16) float W_s[64][68];
    int t = threadIdx.x;
    int p0 = blockIdx.x*64;
    float acc[4][4] = {};
    int tr = t>>4, tc = t&15;
    for (int ck = 0; ck < 2; ck++){
        __syncthreads();
        #pragma unroll
        for (int rep = 0; rep < 4; rep++){
            int idx = rep*256 + t;
            int r = idx>>4, kv = idx&15;
            int p = p0 + r;
            float4 v = make_float4(0.f,0.f,0.f,0.f);
            if (p < N_PTS) v = *(const float4*)&xf[p*CI + ck*64 + kv*4];
            *(float4*)&A_s[r][kv*4] = v;
            *(float4*)&W_s[r][kv*4] = *(const float4*)&Ws[(ck*64 + r)*CO + kv*4];
        }
        __syncthreads();
        #pragma unroll
        for (int kk = 0; kk < 64; kk += 4){
            float4 w0 = *(float4*)&W_s[kk+0][tc*4];
            float4 w1 = *(float4*)&W_s[kk+1][tc*4];
            float4 w2 = *(float4*)&W_s[kk+2][tc*4];
            float4 w3 = *(float4*)&W_s[kk+3][tc*4];
            #pragma unroll
            for (int i = 0; i < 4; i++){
                float4 a = *(float4*)&A_s[tr*4+i][kk];
                mma_row(a, w0, w1, w2, w3, acc[i]);
            }
        }
    }
    #pragma unroll
    for (int i = 0; i < 4; i++){
        int p = p0 + tr*4 + i;
        if (p < N_PTS){
            float4 r;
            r.x = acc[i][0] + bs[tc*4+0];
            r.y = acc[i][1] + bs[tc*4+1];
            r.z = acc[i][2] + bs[tc*4+2];
            r.w = acc[i][3] + bs[tc*4+3];
            *(float4*)&g_skip[p*CO + tc*4] = r;
        }
    }
}

// ---------------- MMA on one staged chunk: A[128][64] x B^T[64][64] fp16 ----------------
__device__ __forceinline__ void mma_chunk64(uint32_t bA, uint32_t bB, int l, int w,
                                            float acc[8][4]){
    uint32_t a[4][4];
    int tile = l>>3, i = l&7;
    int arow = w*16 + (tile&1)*8 + i;
    #pragma unroll
    for (int ks = 0; ks < 4; ks++){
        int acol = ks*16 + (tile>>1)*8;
        ldsm4(a[ks], bA + arow*(A_PAD*2) + acol*2);
    }
    int jj = l>>4, sub = (l>>3)&1, bi = l&7;
    #pragma unroll
    for (int jp = 0; jp < 4; jp++){
        #pragma unroll
        for (int ks = 0; ks < 4; ks++){
            int brow = (2*jp + jj)*8 + bi;
            int bcol = ks*16 + sub*8;
            uint32_t b[4];
            ldsm4(b, bB + brow*(A_PAD*2) + bcol*2);
            mma16816(acc[2*jp],   a[ks], b[0], b[1]);
            mma16816(acc[2*jp+1], a[ks], b[2], b[3]);
        }
    }
}

// ---------------- conv1: 8 folded neighbors x 2 K-chunks = 16 stages, cp.async ring ----------------
__device__ __forceinline__ void conv1_issue(int st, int o, const int* s_nbr, int t, char* dyn){
    int n = st>>1, ck = st&1;
    char* base = dyn + (st%3)*STG_BYTES;
    uint32_t bA = smem_u32(base);
    uint32_t bB = smem_u32(base + SMEM_A_BYTES);
    #pragma unroll
    for (int it = 0; it < 4; it++){
        int lin = it*256 + t, r = lin>>3, c8 = lin&7;
        int nb = s_nbr[n*128 + r];
        const __half* src = (nb >= 0) ? &g_h_h[nb*CI + ck*64 + c8*8] : g_h_h;
        cp_async16(bA + r*(A_PAD*2) + c8*16, src, (nb >= 0) ? 16 : 0);
    }
    #pragma unroll
    for (int it = 0; it < 2; it++){
        int lin = it*256 + t, r = lin>>3, c8 = lin&7;
        cp_async16(bB + r*(A_PAD*2) + c8*16,
                   &g_weffT_h[((o*8+n)*CO + r)*CI + ck*64 + c8*8], 16);
    }
    CP_COMMIT();
}

__global__ __launch_bounds__(256) void k_conv1_mma(const int* __restrict__ coords,
                                                   const float* __restrict__ b1){
    extern __shared__ __align__(16) char dyn[];
    __shared__ int s_nbr[8*128];
    int t = threadIdx.x, l = t&31, w = t>>5;
    int p0 = blockIdx.x*128;
    int o  = blockIdx.y;
    int dx=(o>>2)&1, dy=(o>>1)&1, dz=o&1;

    if (t < 128){
        int p = p0 + t;
        if (p < N_PTS){
            int x=coords[p*4+1], y=coords[p*4+2], z=coords[p*4+3];
            #pragma unroll
            for (int n = 0; n < 8; n++){
                int ox = dx-1+((n>>2)&1), oy = dy-1+((n>>1)&1), oz = dz-1+(n&1);
                s_nbr[n*128 + t] = g_pgrid[((x+ox+1)*GD + (y+oy+1))*GD + (z+oz+1)];
            }
        } else {
            #pragma unroll
            for (int n = 0; n < 8; n++) s_nbr[n*128 + t] = -1;
        }
    }
    __syncthreads();

    conv1_issue(0, o, s_nbr, t, dyn);
    conv1_issue(1, o, s_nbr, t, dyn);

    float acc[8][4] = {};
    for (int st = 0; st < 16; st++){
        if (st == 15) { CP_WAIT(0); } else { CP_WAIT(1); }
        __syncthreads();
        char* base = dyn + (st%3)*STG_BYTES;
        mma_chunk64(smem_u32(base), smem_u32(base + SMEM_A_BYTES), l, w, acc);
        if (st + 2 < 16) conv1_issue(st+2, o, s_nbr, t, dyn);
    }

    int r0 = w*16 + (l>>2);
    #pragma unroll
    for (int j = 0; j < 8; j++){
        int col = j*8 + (l&3)*2;
        int p_0 = p0 + r0;
        if (p_0 < N_PTS){
            float2 v; v.x = acc[j][0] + b1[col]; v.y = acc[j][1] + b1[col+1];
            *(float2*)&g_mid[((size_t)p_0*8 + o)*CO + col] = v;
        }
        int p_1 = p0 + r0 + 8;
        if (p_1 < N_PTS){
            float2 v; v.x = acc[j][2] + b1[col]; v.y = acc[j][3] + b1[col+1];
            *(float2*)&g_mid[((size_t)p_1*8 + o)*CO + col] = v;
        }
    }
}

__global__ void k_stats2(){
    __shared__ float ss[256], ss2[256];
    int t = threadIdx.x; int c = t&63; int lane = t>>6;
    float s=0.f, s2=0.f;
    for (int r = blockIdx.x*4 + lane; r < M_PTS; r += gridDim.x*4){
        float v = g_mid[r*CO + c]; s += v; s2 += v*v;
    }
    ss[t]=s; ss2[t]=s2; __syncthreads();
    if (t < 64){
        float a = ss[t]+ss[t+64]+ss[t+128]+ss[t+192];
        float b = ss2[t]+ss2[t+64]+ss2[t+128]+ss2[t+192];
        atomicAdd(&g_sum2[c], a); atomicAdd(&g_sq2[c], b);
    }
}
__global__ void k_fin2(){
    int g = threadIdx.x;
    if (g < 32){
        float s  = g_sum2[2*g] + g_sum2[2*g+1];
        float s2 = g_sq2[2*g]  + g_sq2[2*g+1];
        float inv = 1.f/(float)(M_PTS*2);
        float mu = s*inv, var = s2*inv - mu*mu;
        g_mu2[g] = mu; g_rs2[g] = rsqrtf(var + 1e-5f);
    }
}
__global__ void k_act(const float* __restrict__ gma, const float* __restrict__ bta){
    int i = blockIdx.x*256 + threadIdx.x;
    int c = i & 63; int g = c >> 1;
    float v = (g_mid[i] - g_mu2[g])*g_rs2[g]*gma[c] + bta[c];
    v = v / (1.f + expf(-v));
    g_act_h[i] = __float2half(v);
}

// ---------------- conv2: 27 taps (K=64 each), cp.async ring, + bias + skip ----------------
__device__ __forceinline__ void conv2_issue(int tap, const int* s_nbr, int t, char* dyn){
    char* base = dyn + (tap%3)*STG_BYTES;
    uint32_t bA = smem_u32(base);
    uint32_t bB = smem_u32(base + SMEM_A_BYTES);
    #pragma unroll
    for (int it = 0; it < 4; it++){
        int lin = it*256 + t, r = lin>>3, c8 = lin&7;
        int nb = s_nbr[tap*128 + r];
        const __half* src = (nb >= 0) ? &g_act_h[nb*CO + c8*8] : g_act_h;
        cp_async16(bA + r*(A_PAD*2) + c8*16, src, (nb >= 0) ? 16 : 0);
    }
    #pragma unroll
    for (int it = 0; it < 2; it++){
        int lin = it*256 + t, r = lin>>3, c8 = lin&7;
        cp_async16(bB + r*(A_PAD*2) + c8*16, &g_w2t_h[(tap*CO + r)*CO + c8*8], 16);
    }
    CP_COMMIT();
}

__global__ __launch_bounds__(256) void k_conv2_mma(const int* __restrict__ coords,
                                                   const float* __restrict__ b2,
                                                   float* __restrict__ out){
    extern __shared__ __align__(16) char dyn[];
    __shared__ int s_nbr[27*128];
    int t = threadIdx.x, l = t&31, w = t>>5;
    int m0 = blockIdx.x*128;     // M_PTS/128 = 1250 exact

    if (t < 128){
        int m = m0 + t, p = m>>3, oo = m&7;
        int cx = 2*coords[p*4+1] + ((oo>>2)&1);
        int cy = 2*coords[p*4+2] + ((oo>>1)&1);
        int cz = 2*coords[p*4+3] + (oo&1);
        #pragma unroll
        for (int tap = 0; tap < 27; tap++){
            int ax = cx + tap/9 - 1;
            int ay = cy + (tap/3)%3 - 1;
            int az = cz + tap%3 - 1;
            int q = g_pgrid[(((ax>>1)+1)*GD + ((ay>>1)+1))*GD + ((az>>1)+1)];
            s_nbr[tap*128 + t] = (q >= 0) ? (q*8 + ((ax&1)<<2) + ((ay&1)<<1) + (az&1)) : -1;
        }
    }
    __syncthreads();

    conv2_issue(0, s_nbr, t, dyn);
    conv2_issue(1, s_nbr, t, dyn);

    float acc[8][4] = {};
    for (int tap = 0; tap < 27; tap++){
        if (tap == 26) { CP_WAIT(0); } else { CP_WAIT(1); }
        __syncthreads();
        char* base = dyn + (tap%3)*STG_BYTES;
        mma_chunk64(smem_u32(base), smem_u32(base + SMEM_A_BYTES), l, w, acc);
        if (tap + 2 < 27) conv2_issue(tap+2, s_nbr, t, dyn);
    }

    int r0 = w*16 + (l>>2);
    #pragma unroll
    for (int j = 0; j < 8; j++){
        int col = j*8 + (l&3)*2;
        {
            int m = m0 + r0, p = m>>3;
            float2 v;
            v.x = acc[j][0] + b2[col]   + g_skip[p*CO + col];
            v.y = acc[j][1] + b2[col+1] + g_skip[p*CO + col+1];
            *(float2*)&out[(size_t)m*CO + col] = v;
        }
        {
            int m = m0 + r0 + 8, p = m>>3;
            float2 v;
            v.x = acc[j][2] + b2[col]   + g_skip[p*CO + col];
            v.y = acc[j][3] + b2[col+1] + g_skip[p*CO + col+1];
            *(float2*)&out[(size_t)m*CO + col] = v;
        }
    }
}

// ---------------- launch ----------------
extern "C" void kernel_launch(void* const* d_in, const int* in_sizes, int n_in,
                              void* d_out, int out_size){
    const float* xf    = (const float*)d_in[0];
    const int*   coords= (const int*)  d_in[1];
    const float* gn1g  = (const float*)d_in[2];
    const float* gn1b  = (const float*)d_in[3];
    const float* W1    = (const float*)d_in[4];
    const float* b1    = (const float*)d_in[5];
    const float* gn2g  = (const float*)d_in[6];
    const float* gn2b  = (const float*)d_in[7];
    const float* W2    = (const float*)d_in[8];
    const float* b2    = (const float*)d_in[9];
    const float* Ws    = (const float*)d_in[10];
    const float* bs    = (const float*)d_in[11];
    float* out = (float*)d_out;

    static int attr_done = 0;
    if (!attr_done){
        cudaFuncSetAttribute(k_conv1_mma, cudaFuncAttributeMaxDynamicSharedMemorySize, SMEM_DYN);
        cudaFuncSetAttribute(k_conv2_mma, cudaFuncAttributeMaxDynamicSharedMemorySize, SMEM_DYN);
        attr_done = 1;
    }

    k_init<<<(GSZ+255)/256, 256>>>();
    k_scatter<<<(N_PTS+255)/256, 256>>>(coords);
    k_stats1<<<160, 128>>>(xf);
    k_fin1<<<1, 32>>>();
    k_h<<<N_PTS*CI/256, 256>>>(xf, gn1g, gn1b);
    k_weffT<<<8*8*CI*CO/256, 256>>>(W1);
    k_w2t<<<(27*CO*CO+255)/256, 256>>>(W2);
    k_skip<<<(N_PTS+63)/64, 256>>>(xf, Ws, bs);
    k_conv1_mma<<<dim3((N_PTS+127)/128, 8), 256, SMEM_DYN>>>(coords, b1);
    k_stats2<<<400, 256>>>();
    k_fin2<<<1, 32>>>();
    k_act<<<M_PTS*CO/256, 256>>>(gn2g, gn2b);
    k_conv2_mma<<<M_PTS/128, 256, SMEM_DYN>>>(coords, b2, out);
}

// round 12
// speedup vs baseline: 2.1471x; 1.0233x over previous
#include <cuda_runtime.h>
#include <cuda_fp16.h>
#include <cstdint>
#include <math.h>

#define N_PTS 20000
#define M_PTS 160000
#define CI 128
#define CO 64
#define GD 34
#define GSZ (GD*GD*GD)

// stage: A 256x64 fp16 (row pad 72 halves = 144B), B 64x64 fp16 (same pad)
#define A_PAD 72
#define SMEM_A_BYTES (256*A_PAD*2)     // 36864
#define SMEM_B_BYTES (64*A_PAD*2)      // 9216
#define STG_BYTES (SMEM_A_BYTES + SMEM_B_BYTES)   // 46080
#define SMEM_DYN (2*STG_BYTES)                     // 92160

// ---------------- device scratch ----------------
__device__ int    g_pgrid[GSZ];
__device__ __align__(16) __half g_h_h[N_PTS*CI];       // silu(gn1(x)) fp16
__device__ float  g_skip[N_PTS*CO];
__device__ float  g_mid[M_PTS*CO];                     // conv1 out fp32
__device__ __align__(16) __half g_act_h[M_PTS*CO];     // silu(gn2(mid)) fp16
__device__ __align__(16) __half g_weffT_h[8*8*CO*CI];  // [o][n][cout][cin]
__device__ __align__(16) __half g_w2t_h[27*CO*CO];     // [tap][cout][cin]
__device__ float g_sum1[CI], g_sq1[CI], g_mu1[32], g_rs1[32];
__device__ float g_sum2[CO], g_sq2[CO], g_mu2[32], g_rs2[32];

// ---------------- helpers ----------------
__device__ __forceinline__ uint32_t smem_u32(const void* p){
    uint32_t a;
    asm("{ .reg .u64 t; cvta.to.shared.u64 t, %1; cvt.u32.u64 %0, t; }" : "=r"(a) : "l"(p));
    return a;
}
__device__ __forceinline__ void cp_async16(uint32_t dst, const void* src, int src_size){
    asm volatile("cp.async.ca.shared.global [%0], [%1], 16, %2;"
                 :: "r"(dst), "l"(src), "r"(src_size) : "memory");
}
#define CP_COMMIT() asm volatile("cp.async.commit_group;" ::: "memory")
#define CP_WAIT(n)  asm volatile("cp.async.wait_group %0;" :: "n"(n) : "memory")

__device__ __forceinline__ void ldsm4(uint32_t* r, uint32_t addr){
    asm volatile("ldmatrix.sync.aligned.m8n8.x4.shared.b16 {%0,%1,%2,%3}, [%4];"
        : "=r"(r[0]),"=r"(r[1]),"=r"(r[2]),"=r"(r[3]) : "r"(addr));
}
__device__ __forceinline__ void mma16816(float* d, const uint32_t* a, uint32_t b0, uint32_t b1){
    asm volatile("mma.sync.aligned.m16n8k16.row.col.f32.f16.f16.f32 "
        "{%0,%1,%2,%3}, {%4,%5,%6,%7}, {%8,%9}, {%0,%1,%2,%3};"
        : "+f"(d[0]),"+f"(d[1]),"+f"(d[2]),"+f"(d[3])
        : "r"(a[0]),"r"(a[1]),"r"(a[2]),"r"(a[3]), "r"(b0),"r"(b1));
}

// ---------------- small kernels ----------------
__global__ void k_init(){
    int i = blockIdx.x*256 + threadIdx.x;
    if (i < GSZ) g_pgrid[i] = -1;
    if (i < CI){ g_sum1[i]=0.f; g_sq1[i]=0.f; }
    if (i < CO){ g_sum2[i]=0.f; g_sq2[i]=0.f; }
}
__global__ void k_scatter(const int* __restrict__ coords){
    int p = blockIdx.x*256 + threadIdx.x;
    if (p < N_PTS){
        int x=coords[p*4+1], y=coords[p*4+2], z=coords[p*4+3];
        g_pgrid[((x+1)*GD + (y+1))*GD + (z+1)] = p;
    }
}
__global__ void k_stats1(const float* __restrict__ xf){
    int c = threadIdx.x;
    float s=0.f, s2=0.f;
    for (int r = blockIdx.x; r < N_PTS; r += gridDim.x){
        float v = xf[r*CI + c]; s += v; s2 += v*v;
    }
    atomicAdd(&g_sum1[c], s); atomicAdd(&g_sq1[c], s2);
}
__global__ void k_fin1(){
    int g = threadIdx.x;
    if (g < 32){
        float s=0.f, s2=0.f;
        for (int j=0;j<4;j++){ s += g_sum1[g*4+j]; s2 += g_sq1[g*4+j]; }
        float inv = 1.f/(float)(N_PTS*4);
        float mu = s*inv, var = s2*inv - mu*mu;
        g_mu1[g] = mu; g_rs1[g] = rsqrtf(var + 1e-5f);
    }
}
__global__ void k_h(const float* __restrict__ xf,
                    const float* __restrict__ gma, const float* __restrict__ bta){
    int i = blockIdx.x*256 + threadIdx.x;
    int c = i & (CI-1); int g = c >> 2;
    float v = (xf[i] - g_mu1[g])*g_rs1[g]*gma[c] + bta[c];
    v = v / (1.f + expf(-v));
    g_h_h[i] = __float2half(v);
}
__global__ void k_weffT(const float* __restrict__ W1){
    int idx = blockIdx.x*256 + threadIdx.x;   // 8*8*128*64
    int cout = idx & 63, cin = (idx>>6)&127, n = (idx>>13)&7, o = idx>>16;
    int d0=(o>>2)&1, d1=(o>>1)&1, d2=o&1;
    int n0=(n>>2)&1, n1=(n>>1)&1, n2=n&1;
    float s = 0.f;
    for (int i=0;i<3;i++){
        int t0=d0+i-1; int p0=(t0>=2)?1:((t0>=0)?0:-1);
        if (p0 - d0 + 1 != n0) continue;
        for (int j=0;j<3;j++){
            int t1=d1+j-1; int p1=(t1>=2)?1:((t1>=0)?0:-1);
            if (p1 - d1 + 1 != n1) continue;
            for (int k=0;k<3;k++){
                int t2=d2+k-1; int p2=(t2>=2)?1:((t2>=0)?0:-1);
                if (p2 - d2 + 1 != n2) continue;
                s += W1[(((i*3+j)*3+k)*CI + cin)*CO + cout];
            }
        }
    }
    g_weffT_h[((o*8+n)*CO + cout)*CI + cin] = __float2half(s);
}
__global__ void k_w2t(const float* __restrict__ W2){
    int idx = blockIdx.x*256 + threadIdx.x;   // 27*64*64
    if (idx >= 27*CO*CO) return;
    int cout = idx & 63, cin = (idx>>6)&63, tap = idx>>12;
    g_w2t_h[(tap*CO + cout)*CO + cin] = __float2half(W2[(tap*CO + cin)*CO + cout]);
}

// ---------------- skip GEMM (scalar fp32, tiny, exact) ----------------
__device__ __forceinline__ void mma_row(float4 a, float4 w0, float4 w1, float4 w2, float4 w3,
                                        float acc[4]){
    acc[0]=fmaf(a.x,w0.x,acc[0]); acc[0]=fmaf(a.y,w1.x,acc[0]); acc[0]=fmaf(a.z,w2.x,acc[0]); acc[0]=fmaf(a.w,w3.x,acc[0]);
    acc[1]=fmaf(a.x,w0.y,acc[1]); acc[1]=fmaf(a.y,w1.y,acc[1]); acc[1]=fmaf(a.z,w2.y,acc[1]); acc[1]=fmaf(a.w,w3.y,acc[1]);
    acc[2]=fmaf(a.x,w0.z,acc[2]); acc[2]=fmaf(a.y,w1.z,acc[2]); acc[2]=fmaf(a.z,w2.z,acc[2]); acc[2]=fmaf(a.w,w3.z,acc[2]);
    acc[3]=fmaf(a.x,w0.w,acc[3]); acc[3]=fmaf(a.y,w1.w,acc[3]); acc[3]=fmaf(a.z,w2.w,acc[3]); acc[3]=fmaf(a.w,w3.w,acc[3]);
}
__global__ __launch_bounds__(256) void k_skip(const float* __restrict__ xf,
                                              const float* __restrict__ Ws,
                                              const float* __restrict__ bs){
    __shared__ __align__(16) float A_s[64][68];
    __shared__ __align__(16) float W_s[64][68];
    int t = threadIdx.x;
    int p0 = blockIdx.x*64;
    float acc[4][4] = {};
    int tr = t>>4, tc = t&15;
    for (int ck = 0; ck < 2; ck++){
        __syncthreads();
        #pragma unroll
        for (int rep = 0; rep < 4; rep++){
            int idx = rep*256 + t;
            int r = idx>>4, kv = idx&15;
            int p = p0 + r;
            float4 v = make_float4(0.f,0.f,0.f,0.f);
            if (p < N_PTS) v = *(const float4*)&xf[p*CI + ck*64 + kv*4];
            *(float4*)&A_s[r][kv*4] = v;
            *(float4*)&W_s[r][kv*4] = *(const float4*)&Ws[(ck*64 + r)*CO + kv*4];
        }
        __syncthreads();
        #pragma unroll
        for (int kk = 0; kk < 64; kk += 4){
            float4 w0 = *(float4*)&W_s[kk+0][tc*4];
            float4 w1 = *(float4*)&W_s[kk+1][tc*4];
            float4 w2 = *(float4*)&W_s[kk+2][tc*4];
            float4 w3 = *(float4*)&W_s[kk+3][tc*4];
            #pragma unroll
            for (int i = 0; i < 4; i++){
                float4 a = *(float4*)&A_s[tr*4+i][kk];
                mma_row(a, w0, w1, w2, w3, acc[i]);
            }
        }
    }
    #pragma unroll
    for (int i = 0; i < 4; i++){
        int p = p0 + tr*4 + i;
        if (p < N_PTS){
            float4 r;
            r.x = acc[i][0] + bs[tc*4+0];
            r.y = acc[i][1] + bs[tc*4+1];
            r.z = acc[i][2] + bs[tc*4+2];
            r.w = acc[i][3] + bs[tc*4+3];
            *(float4*)&g_skip[p*CO + tc*4] = r;
        }
    }
}

// ---------------- MMA on one staged chunk: A[256][64] x B^T[64][64] fp16 ----------------
// warp grid 4(M)x2(N): warp tile 64 rows x 32 cols; acc[16][4] (mt*4+nt)
// Lane mapping (both A and B): lanes 0-15 -> rows +0..15 at col base; lanes 16-31 ->
// same rows at col base +16B. Returned ldsm4 regs are therefore ordered:
//   [ (r0-7,k0-7), (r8-15,k0-7), (r0-7,k8-15), (r8-15,k8-15) ]
// => A fragment uses a[0..3] directly; B n8-fragments pair {b[0],b[2]} and {b[1],b[3]}.
__device__ __forceinline__ void mma_chunk256(uint32_t bA, uint32_t bB, int l, int w,
                                             float acc[16][4]){
    int mi = w>>1, ni = w&1;
    int lr = l&15, lc = l>>4;
    #pragma unroll
    for (int ks = 0; ks < 4; ks++){
        int colb = ks*32 + lc*16;     // byte offset within row
        uint32_t a[4][4];
        #pragma unroll
        for (int mt = 0; mt < 4; mt++){
            int row = mi*64 + mt*16 + lr;
            ldsm4(a[mt], bA + row*(A_PAD*2) + colb);
        }
        #pragma unroll
        for (int bt = 0; bt < 2; bt++){
            uint32_t b[4];
            int brow = ni*32 + bt*16 + lr;
            ldsm4(b, bB + brow*(A_PAD*2) + colb);
            #pragma unroll
            for (int mt = 0; mt < 4; mt++){
                mma16816(acc[mt*4 + bt*2],     a[mt], b[0], b[2]);
                mma16816(acc[mt*4 + bt*2 + 1], a[mt], b[1], b[3]);
            }
        }
    }
}

// ---------------- conv1: 8 folded neighbors x 2 K-chunks = 16 stages, 2-stage cp.async ----------------
__device__ __forceinline__ void conv1_issue(int st, int o, const int* s_nbr, int t, char* dyn){
    int n = st>>1, ck = st&1;
    char* base = dyn + (st&1)*STG_BYTES;
    uint32_t bA = smem_u32(base);
    uint32_t bB = smem_u32(base + SMEM_A_BYTES);
    int rr = t>>3, c8 = t&7;
    #pragma unroll
    for (int it = 0; it < 8; it++){
        int r = it*32 + rr;
        int nb = s_nbr[n*256 + r];
        const __half* src = (nb >= 0) ? &g_h_h[nb*CI + ck*64 + c8*8] : g_h_h;
        cp_async16(bA + r*(A_PAD*2) + c8*16, src, (nb >= 0) ? 16 : 0);
    }
    #pragma unroll
    for (int it = 0; it < 2; it++){
        int r = it*32 + rr;
        cp_async16(bB + r*(A_PAD*2) + c8*16,
                   &g_weffT_h[((o*8+n)*CO + r)*CI + ck*64 + c8*8], 16);
    }
    CP_COMMIT();
}

__global__ __launch_bounds__(256,2) void k_conv1_mma(const int* __restrict__ coords,
                                                     const float* __restrict__ b1){
    extern __shared__ __align__(16) char dyn[];
    __shared__ int s_nbr[8*256];
    int t = threadIdx.x, l = t&31, w = t>>5;
    int p0 = blockIdx.x*256;
    int o  = blockIdx.y;
    int dx=(o>>2)&1, dy=(o>>1)&1, dz=o&1;

    {   // each thread handles row r=t for all 8 neighbors
        int p = p0 + t;
        if (p < N_PTS){
            int x=coords[p*4+1], y=coords[p*4+2], z=coords[p*4+3];
            #pragma unroll
            for (int n = 0; n < 8; n++){
                int ox = dx-1+((n>>2)&1), oy = dy-1+((n>>1)&1), oz = dz-1+(n&1);
                s_nbr[n*256 + t] = g_pgrid[((x+ox+1)*GD + (y+oy+1))*GD + (z+oz+1)];
            }
        } else {
            #pragma unroll
            for (int n = 0; n < 8; n++) s_nbr[n*256 + t] = -1;
        }
    }
    __syncthreads();

    conv1_issue(0, o, s_nbr, t, dyn);

    float acc[16][4] = {};
    for (int st = 0; st < 16; st++){
        if (st + 1 < 16){ conv1_issue(st+1, o, s_nbr, t, dyn); CP_WAIT(1); }
        else            { CP_WAIT(0); }
        __syncthreads();
        char* base = dyn + (st&1)*STG_BYTES;
        mma_chunk256(smem_u32(base), smem_u32(base + SMEM_A_BYTES), l, w, acc);
        __syncthreads();
    }

    int mi = w>>1, ni = w&1;
    #pragma unroll
    for (int mt = 0; mt < 4; mt++){
        #pragma unroll
        for (int nt = 0; nt < 4; nt++){
            float* ac = acc[mt*4+nt];
            int row0 = mi*64 + mt*16 + (l>>2);
            int col  = ni*32 + nt*8 + (l&3)*2;
            int p_0 = p0 + row0;
            if (p_0 < N_PTS){
                float2 v; v.x = ac[0] + b1[col]; v.y = ac[1] + b1[col+1];
                *(float2*)&g_mid[((size_t)p_0*8 + o)*CO + col] = v;
            }
            int p_1 = p0 + row0 + 8;
            if (p_1 < N_PTS){
                float2 v; v.x = ac[2] + b1[col]; v.y = ac[3] + b1[col+1];
                *(float2*)&g_mid[((size_t)p_1*8 + o)*CO + col] = v;
            }
        }
    }
}

__global__ void k_stats2(){
    __shared__ float ss[256], ss2[256];
    int t = threadIdx.x; int c = t&63; int lane = t>>6;
    float s=0.f, s2=0.f;
    for (int r = blockIdx.x*4 + lane; r < M_PTS; r += gridDim.x*4){
        float v = g_mid[r*CO + c]; s += v; s2 += v*v;
    }
    ss[t]=s; ss2[t]=s2; __syncthreads();
    if (t < 64){
        float a = ss[t]+ss[t+64]+ss[t+128]+ss[t+192];
        float b = ss2[t]+ss2[t+64]+ss2[t+128]+ss2[t+192];
        atomicAdd(&g_sum2[c], a); atomicAdd(&g_sq2[c], b);
    }
}
__global__ void k_fin2(){
    int g = threadIdx.x;
    if (g < 32){
        float s  = g_sum2[2*g] + g_sum2[2*g+1];
        float s2 = g_sq2[2*g]  + g_sq2[2*g+1];
        float inv = 1.f/(float)(M_PTS*2);
        float mu = s*inv, var = s2*inv - mu*mu;
        g_mu2[g] = mu; g_rs2[g] = rsqrtf(var + 1e-5f);
    }
}
__global__ void k_act(const float* __restrict__ gma, const float* __restrict__ bta){
    int i = blockIdx.x*256 + threadIdx.x;
    int c = i & 63; int g = c >> 1;
    float v = (g_mid[i] - g_mu2[g])*g_rs2[g]*gma[c] + bta[c];
    v = v / (1.f + expf(-v));
    g_act_h[i] = __float2half(v);
}

// ---------------- conv2: 27 taps, 2-stage cp.async, parent-neighbor table ----------------
__device__ __forceinline__ void conv2_issue(int tap, const int* s_pnbr, int t, char* dyn){
    char* base = dyn + (tap&1)*STG_BYTES;
    uint32_t bA = smem_u32(base);
    uint32_t bB = smem_u32(base + SMEM_A_BYTES);
    int rr = t>>3, c8 = t&7;
    int o = rr & 7;                                  // child parity — constant per thread across iters
    int tx = tap/9, ty = (tap/3)%3, tz = tap%3;
    int sx = ((o>>2)&1) + tx - 1, sy = ((o>>1)&1) + ty - 1, sz = (o&1) + tz - 1;
    int n3 = ((sx>>1)+1)*9 + ((sy>>1)+1)*3 + ((sz>>1)+1);
    int par = (sx&1)*4 + (sy&1)*2 + (sz&1);
    #pragma unroll
    for (int it = 0; it < 8; it++){
        int r = it*32 + rr;
        int pi = r>>3;                               // parent slot 0..31
        int q = s_pnbr[pi*27 + n3];
        int nb = (q >= 0) ? q*8 + par : -1;
        const __half* src = (nb >= 0) ? &g_act_h[nb*CO + c8*8] : g_act_h;
        cp_async16(bA + r*(A_PAD*2) + c8*16, src, (nb >= 0) ? 16 : 0);
    }
    #pragma unroll
    for (int it = 0; it < 2; it++){
        int r = it*32 + rr;
        cp_async16(bB + r*(A_PAD*2) + c8*16, &g_w2t_h[(tap*CO + r)*CO + c8*8], 16);
    }
    CP_COMMIT();
}

__global__ __launch_bounds__(256,2) void k_conv2_mma(const int* __restrict__ coords,
                                                     const float* __restrict__ b2,
                                                     float* __restrict__ out){
    extern __shared__ __align__(16) char dyn[];
    __shared__ int s_pnbr[32*27];
    int t = threadIdx.x, l = t&31, w = t>>5;
    int m0 = blockIdx.x*256;     // M_PTS/256 = 625 exact
    int pbase = m0 >> 3;         // 32 parents per tile

    for (int e = t; e < 32*27; e += 256){
        int pl = e/27, n3 = e - pl*27;
        int p = pbase + pl;
        int ox = n3/9 - 1, oy = (n3/3)%3 - 1, oz = n3%3 - 1;
        int x = coords[p*4+1], y = coords[p*4+2], z = coords[p*4+3];
        s_pnbr[e] = g_pgrid[((x+ox+1)*GD + (y+oy+1))*GD + (z+oz+1)];
    }
    __syncthreads();

    conv2_issue(0, s_pnbr, t, dyn);

    float acc[16][4] = {};
    for (int tap = 0; tap < 27; tap++){
        if (tap + 1 < 27){ conv2_issue(tap+1, s_pnbr, t, dyn); CP_WAIT(1); }
        else             { CP_WAIT(0); }
        __syncthreads();
        char* base = dyn + (tap&1)*STG_BYTES;
        mma_chunk256(smem_u32(base), smem_u32(base + SMEM_A_BYTES), l, w, acc);
        __syncthreads();
    }

    int mi = w>>1, ni = w&1;
    #pragma unroll
    for (int mt = 0; mt < 4; mt++){
        #pragma unroll
        for (int nt = 0; nt < 4; nt++){
            float* ac = acc[mt*4+nt];
            int row0 = mi*64 + mt*16 + (l>>2);
            int col  = ni*32 + nt*8 + (l&3)*2;
            {
                int m = m0 + row0, p = m>>3;
                float2 v;
                v.x = ac[0] + b2[col]   + g_skip[p*CO + col];
                v.y = ac[1] + b2[col+1] + g_skip[p*CO + col+1];
                *(float2*)&out[(size_t)m*CO + col] = v;
            }
            {
                int m = m0 + row0 + 8, p = m>>3;
                float2 v;
                v.x = ac[2] + b2[col]   + g_skip[p*CO + col];
                v.y = ac[3] + b2[col+1] + g_skip[p*CO + col+1];
                *(float2*)&out[(size_t)m*CO + col] = v;
            }
        }
    }
}

// ---------------- launch ----------------
extern "C" void kernel_launch(void* const* d_in, const int* in_sizes, int n_in,
                              void* d_out, int out_size){
    const float* xf    = (const float*)d_in[0];
    const int*   coords= (const int*)  d_in[1];
    const float* gn1g  = (const float*)d_in[2];
    const float* gn1b  = (const float*)d_in[3];
    const float* W1    = (const float*)d_in[4];
    const float* b1    = (const float*)d_in[5];
    const float* gn2g  = (const float*)d_in[6];
    const float* gn2b  = (const float*)d_in[7];
    const float* W2    = (const float*)d_in[8];
    const float* b2    = (const float*)d_in[9];
    const float* Ws    = (const float*)d_in[10];
    const float* bs    = (const float*)d_in[11];
    float* out = (float*)d_out;

    static int attr_done = 0;
    if (!attr_done){
        cudaFuncSetAttribute(k_conv1_mma, cudaFuncAttributeMaxDynamicSharedMemorySize, SMEM_DYN);
        cudaFuncSetAttribute(k_conv2_mma, cudaFuncAttributeMaxDynamicSharedMemorySize, SMEM_DYN);
        attr_done = 1;
    }

    k_init<<<(GSZ+255)/256, 256>>>();
    k_scatter<<<(N_PTS+255)/256, 256>>>(coords);
    k_stats1<<<160, 128>>>(xf);
    k_fin1<<<1, 32>>>();
    k_h<<<N_PTS*CI/256, 256>>>(xf, gn1g, gn1b);
    k_weffT<<<8*8*CI*CO/256, 256>>>(W1);
    k_w2t<<<(27*CO*CO+255)/256, 256>>>(W2);
    k_skip<<<(N_PTS+63)/64, 256>>>(xf, Ws, bs);
    k_conv1_mma<<<dim3((N_PTS+255)/256, 8), 256, SMEM_DYN>>>(coords, b1);
    k_stats2<<<400, 256>>>();
    k_fin2<<<1, 32>>>();
    k_act<<<M_PTS*CO/256, 256>>>(gn2g, gn2b);
    k_conv2_mma<<<M_PTS/256, 256, SMEM_DYN>>>(coords, b2, out);
}

// round 14
// speedup vs baseline: 2.7703x; 1.2903x over previous
#include <cuda_runtime.h>
#include <cuda_fp16.h>
#include <cstdint>
#include <math.h>

#define N_PTS 20000
#define M_PTS 160000
#define CI 128
#define CO 64
#define GD 34
#define GSZ (GD*GD*GD)

// stage: A 256x64 fp16 (row pad 72 halves = 144B), B 64x64 fp16 (same pad)
#define A_PAD 72
#define SMEM_A_BYTES (256*A_PAD*2)     // 36864
#define SMEM_B_BYTES (64*A_PAD*2)      // 9216
#define STG_BYTES (SMEM_A_BYTES + SMEM_B_BYTES)   // 46080
#define SMEM_DYN (2*STG_BYTES)                     // 92160

// ---------------- device scratch ----------------
__device__ int    g_pgrid[GSZ];
__device__ __align__(16) __half g_h_h[N_PTS*CI];       // silu(gn1(x)) fp16
__device__ float  g_skip[N_PTS*CO];
__device__ float  g_mid[M_PTS*CO];                     // conv1 out fp32
__device__ __align__(16) __half g_act_h[M_PTS*CO];     // silu(gn2(mid)) fp16
__device__ __align__(16) __half g_weffT_h[8*8*CO*CI];  // [o][n][cout][cin]
__device__ __align__(16) __half g_w2t_h[27*CO*CO];     // [tap][cout][cin]
__device__ float g_sum1[CI], g_sq1[CI];
__device__ float g_sum2[CO], g_sq2[CO];

// ---------------- helpers ----------------
__device__ __forceinline__ uint32_t smem_u32(const void* p){
    uint32_t a;
    asm("{ .reg .u64 t; cvta.to.shared.u64 t, %1; cvt.u32.u64 %0, t; }" : "=r"(a) : "l"(p));
    return a;
}
__device__ __forceinline__ void cp_async16(uint32_t dst, const void* src, int src_size){
    asm volatile("cp.async.ca.shared.global [%0], [%1], 16, %2;"
                 :: "r"(dst), "l"(src), "r"(src_size) : "memory");
}
#define CP_COMMIT() asm volatile("cp.async.commit_group;" ::: "memory")
#define CP_WAIT(n)  asm volatile("cp.async.wait_group %0;" :: "n"(n) : "memory")

__device__ __forceinline__ void ldsm4(uint32_t* r, uint32_t addr){
    asm volatile("ldmatrix.sync.aligned.m8n8.x4.shared.b16 {%0,%1,%2,%3}, [%4];"
        : "=r"(r[0]),"=r"(r[1]),"=r"(r[2]),"=r"(r[3]) : "r"(addr));
}
__device__ __forceinline__ void mma16816(float* d, const uint32_t* a, uint32_t b0, uint32_t b1){
    asm volatile("mma.sync.aligned.m16n8k16.row.col.f32.f16.f16.f32 "
        "{%0,%1,%2,%3}, {%4,%5,%6,%7}, {%8,%9}, {%0,%1,%2,%3};"
        : "+f"(d[0]),"+f"(d[1]),"+f"(d[2]),"+f"(d[3])
        : "r"(a[0]),"r"(a[1]),"r"(a[2]),"r"(a[3]), "r"(b0),"r"(b1));
}

// ---------------- kernel 1: init ----------------
__global__ void k_init(){
    int i = blockIdx.x*256 + threadIdx.x;
    if (i < GSZ) g_pgrid[i] = -1;
    if (i < CI){ g_sum1[i]=0.f; g_sq1[i]=0.f; }
    if (i < CO){ g_sum2[i]=0.f; g_sq2[i]=0.f; }
}

// ---------------- kernel 2: scatter + stats1 ----------------
__global__ void k_front(const int* __restrict__ coords, const float* __restrict__ xf){
    int b = blockIdx.x, t = threadIdx.x;
    if (b < 79){
        int p = b*256 + t;
        if (p < N_PTS){
            int x=coords[p*4+1], y=coords[p*4+2], z=coords[p*4+3];
            g_pgrid[((x+1)*GD + (y+1))*GD + (z+1)] = p;
        }
    } else {
        int bi = b - 79;                 // 0..159
        int c = t & 127;
        int sId = bi + 160*(t>>7);       // 0..319
        float s=0.f, s2=0.f;
        for (int r = sId; r < N_PTS; r += 320){
            float v = xf[r*CI + c]; s += v; s2 += v*v;
        }
        atomicAdd(&g_sum1[c], s); atomicAdd(&g_sq1[c], s2);
    }
}

// ---------------- kernel 3: prep = weffT | w2t | h(+fin1 inline) ----------------
__global__ void k_prep(const float* __restrict__ W1, const float* __restrict__ W2,
                       const float* __restrict__ xf,
                       const float* __restrict__ gma, const float* __restrict__ bta){
    int b = blockIdx.x, t = threadIdx.x;
    if (b < 2048){
        int idx = b*256 + t;   // 8*8*128*64
        int cout = idx & 63, cin = (idx>>6)&127, n = (idx>>13)&7, o = idx>>16;
        int d0=(o>>2)&1, d1=(o>>1)&1, d2=o&1;
        int n0=(n>>2)&1, n1=(n>>1)&1, n2=n&1;
        float s = 0.f;
        for (int i=0;i<3;i++){
            int t0=d0+i-1; int p0=(t0>=2)?1:((t0>=0)?0:-1);
            if (p0 - d0 + 1 != n0) continue;
            for (int j=0;j<3;j++){
                int t1=d1+j-1; int p1=(t1>=2)?1:((t1>=0)?0:-1);
                if (p1 - d1 + 1 != n1) continue;
                for (int k=0;k<3;k++){
                    int t2=d2+k-1; int p2=(t2>=2)?1:((t2>=0)?0:-1);
                    if (p2 - d2 + 1 != n2) continue;
                    s += W1[(((i*3+j)*3+k)*CI + cin)*CO + cout];
                }
            }
        }
        g_weffT_h[((o*8+n)*CO + cout)*CI + cin] = __float2half(s);
    } else if (b < 2480){
        int idx = (b-2048)*256 + t;   // 27*64*64 = 110592
        if (idx < 27*CO*CO){
            int cout = idx & 63, cin = (idx>>6)&63, tap = idx>>12;
            g_w2t_h[(tap*CO + cout)*CO + cin] = __float2half(W2[(tap*CO + cin)*CO + cout]);
        }
    } else {
        __shared__ float smu[32], srs[32];
        if (t < 32){
            float s=0.f, s2=0.f;
            #pragma unroll
            for (int j=0;j<4;j++){ s += g_sum1[t*4+j]; s2 += g_sq1[t*4+j]; }
            float inv = 1.f/(float)(N_PTS*4);
            float mu = s*inv, var = s2*inv - mu*mu;
            smu[t] = mu; srs[t] = rsqrtf(var + 1e-5f);
        }
        __syncthreads();
        int i = (b-2480)*256 + t;     // N_PTS*CI = 2560000, 10000 blocks exact
        int c = i & (CI-1); int g = c >> 2;
        float v = (xf[i] - smu[g])*srs[g]*gma[c] + bta[c];
        v = v / (1.f + expf(-v));
        g_h_h[i] = __float2half(v);
    }
}

// ---------------- skip tile (device fn, fp32 FFMA; runs in conv1 grid y==8) ----------------
__device__ __forceinline__ void mma_row(float4 a, float4 w0, float4 w1, float4 w2, float4 w3,
                                        float acc[4]){
    acc[0]=fmaf(a.x,w0.x,acc[0]); acc[0]=fmaf(a.y,w1.x,acc[0]); acc[0]=fmaf(a.z,w2.x,acc[0]); acc[0]=fmaf(a.w,w3.x,acc[0]);
    acc[1]=fmaf(a.x,w0.y,acc[1]); acc[1]=fmaf(a.y,w1.y,acc[1]); acc[1]=fmaf(a.z,w2.y,acc[1]); acc[1]=fmaf(a.w,w3.y,acc[1]);
    acc[2]=fmaf(a.x,w0.z,acc[2]); acc[2]=fmaf(a.y,w1.z,acc[2]); acc[2]=fmaf(a.z,w2.z,acc[2]); acc[2]=fmaf(a.w,w3.z,acc[2]);
    acc[3]=fmaf(a.x,w0.w,acc[3]); acc[3]=fmaf(a.y,w1.w,acc[3]); acc[3]=fmaf(a.z,w2.w,acc[3]); acc[3]=fmaf(a.w,w3.w,acc[3]);
}
__device__ void skip_tile(const float* __restrict__ xf, const float* __restrict__ Ws,
                          const float* __restrict__ bs, int p0, int t, char* dyn){
    float (*A_s)[68] = (float(*)[68])dyn;
    float (*W_s)[68] = (float(*)[68])(dyn + 64*68*4);
    float acc[4][4] = {};
    int tr = t>>4, tc = t&15;
    for (int ck = 0; ck < 2; ck++){
        __syncthreads();
        #pragma unroll
        for (int rep = 0; rep < 4; rep++){
            int idx = rep*256 + t;
            int r = idx>>4, kv = idx&15;
            int p = p0 + r;
            float4 v = make_float4(0.f,0.f,0.f,0.f);
            if (p < N_PTS) v = *(const float4*)&xf[p*CI + ck*64 + kv*4];
            *(float4*)&A_s[r][kv*4] = v;
            *(float4*)&W_s[r][kv*4] = *(const float4*)&Ws[(ck*64 + r)*CO + kv*4];
        }
        __syncthreads();
        #pragma unroll
        for (int kk = 0; kk < 64; kk += 4){
            float4 w0 = *(float4*)&W_s[kk+0][tc*4];
            float4 w1 = *(float4*)&W_s[kk+1][tc*4];
            float4 w2 = *(float4*)&W_s[kk+2][tc*4];
            float4 w3 = *(float4*)&W_s[kk+3][tc*4];
            #pragma unroll
            for (int i = 0; i < 4; i++){
                float4 a = *(float4*)&A_s[tr*4+i][kk];
                mma_row(a, w0, w1, w2, w3, acc[i]);
            }
        }
    }
    #pragma unroll
    for (int i = 0; i < 4; i++){
        int p = p0 + tr*4 + i;
        if (p < N_PTS){
            float4 r;
            r.x = acc[i][0] + bs[tc*4+0];
            r.y = acc[i][1] + bs[tc*4+1];
            r.z = acc[i][2] + bs[tc*4+2];
            r.w = acc[i][3] + bs[tc*4+3];
            *(float4*)&g_skip[p*CO + tc*4] = r;
        }
    }
}

// ---------------- MMA on one staged chunk: A[256][64] x B^T[64][64] fp16 ----------------
// Lane mapping (A and B): lanes 0-15 -> rows +0..15 at col base; lanes 16-31 -> same rows
// at col base +16B. ldsm4 regs: [ (r0-7,k0-7), (r8-15,k0-7), (r0-7,k8-15), (r8-15,k8-15) ]
// => B n8-fragments pair {b[0],b[2]} and {b[1],b[3]}.
__device__ __forceinline__ void mma_chunk256(uint32_t bA, uint32_t bB, int l, int w,
                                             float acc[16][4]){
    int mi = w>>1, ni = w&1;
    int lr = l&15, lc = l>>4;
    #pragma unroll
    for (int ks = 0; ks < 4; ks++){
        int colb = ks*32 + lc*16;
        uint32_t a[4][4];
        #pragma unroll
        for (int mt = 0; mt < 4; mt++){
            int row = mi*64 + mt*16 + lr;
            ldsm4(a[mt], bA + row*(A_PAD*2) + colb);
        }
        #pragma unroll
        for (int bt = 0; bt < 2; bt++){
            uint32_t b[4];
            int brow = ni*32 + bt*16 + lr;
            ldsm4(b, bB + brow*(A_PAD*2) + colb);
            #pragma unroll
            for (int mt = 0; mt < 4; mt++){
                mma16816(acc[mt*4 + bt*2],     a[mt], b[0], b[2]);
                mma16816(acc[mt*4 + bt*2 + 1], a[mt], b[1], b[3]);
            }
        }
    }
}

// ---------------- kernel 4: conv1 (+ skip on y==8, + stats2 in epilogue) ----------------
__device__ __forceinline__ void conv1_issue(int st, int o, const int* s_nbr, int t, char* dyn){
    int n = st>>1, ck = st&1;
    char* base = dyn + (st&1)*STG_BYTES;
    uint32_t bA = smem_u32(base);
    uint32_t bB = smem_u32(base + SMEM_A_BYTES);
    int rr = t>>3, c8 = t&7;
    #pragma unroll
    for (int it = 0; it < 8; it++){
        int r = it*32 + rr;
        int nb = s_nbr[n*256 + r];
        const __half* src = (nb >= 0) ? &g_h_h[nb*CI + ck*64 + c8*8] : g_h_h;
        cp_async16(bA + r*(A_PAD*2) + c8*16, src, (nb >= 0) ? 16 : 0);
    }
    #pragma unroll
    for (int it = 0; it < 2; it++){
        int r = it*32 + rr;
        cp_async16(bB + r*(A_PAD*2) + c8*16,
                   &g_weffT_h[((o*8+n)*CO + r)*CI + ck*64 + c8*8], 16);
    }
    CP_COMMIT();
}

__global__ __launch_bounds__(256,2) void k_conv1_mma(const int* __restrict__ coords,
                                                     const float* __restrict__ b1,
                                                     const float* __restrict__ xf,
                                                     const float* __restrict__ Ws,
                                                     const float* __restrict__ bs){
    extern __shared__ __align__(16) char dyn[];
    __shared__ int s_nbr[8*256];
    int t = threadIdx.x, l = t&31, w = t>>5;

    if (blockIdx.y == 8){   // skip GEMM filler: 79 blocks x 256 rows
        #pragma unroll
        for (int c = 0; c < 4; c++)
            skip_tile(xf, Ws, bs, blockIdx.x*256 + c*64, t, dyn);
        return;
    }

    int p0 = blockIdx.x*256;
    int o  = blockIdx.y;
    int dx=(o>>2)&1, dy=(o>>1)&1, dz=o&1;

    {
        int p = p0 + t;
        if (p < N_PTS){
            int x=coords[p*4+1], y=coords[p*4+2], z=coords[p*4+3];
            #pragma unroll
            for (int n = 0; n < 8; n++){
                int ox = dx-1+((n>>2)&1), oy = dy-1+((n>>1)&1), oz = dz-1+(n&1);
                s_nbr[n*256 + t] = g_pgrid[((x+ox+1)*GD + (y+oy+1))*GD + (z+oz+1)];
            }
        } else {
            #pragma unroll
            for (int n = 0; n < 8; n++) s_nbr[n*256 + t] = -1;
        }
    }
    __syncthreads();

    conv1_issue(0, o, s_nbr, t, dyn);

    float acc[16][4] = {};
    for (int st = 0; st < 16; st++){
        if (st + 1 < 16){ conv1_issue(st+1, o, s_nbr, t, dyn); CP_WAIT(1); }
        else            { CP_WAIT(0); }
        __syncthreads();
        char* base = dyn + (st&1)*STG_BYTES;
        mma_chunk256(smem_u32(base), smem_u32(base + SMEM_A_BYTES), l, w, acc);
        __syncthreads();
    }

    int mi = w>>1, ni = w&1;
    float s[8] = {}, s2[8] = {};
    #pragma unroll
    for (int mt = 0; mt < 4; mt++){
        #pragma unroll
        for (int nt = 0; nt < 4; nt++){
            float* ac = acc[mt*4+nt];
            int row0 = mi*64 + mt*16 + (l>>2);
            int col  = ni*32 + nt*8 + (l&3)*2;
            int p_0 = p0 + row0;
            if (p_0 < N_PTS){
                float2 v; v.x = ac[0] + b1[col]; v.y = ac[1] + b1[col+1];
                *(float2*)&g_mid[((size_t)p_0*8 + o)*CO + col] = v;
                s[nt*2+0] += v.x; s2[nt*2+0] += v.x*v.x;
                s[nt*2+1] += v.y; s2[nt*2+1] += v.y*v.y;
            }
            int p_1 = p0 + row0 + 8;
            if (p_1 < N_PTS){
                float2 v; v.x = ac[2] + b1[col]; v.y = ac[3] + b1[col+1];
                *(float2*)&g_mid[((size_t)p_1*8 + o)*CO + col] = v;
                s[nt*2+0] += v.x; s2[nt*2+0] += v.x*v.x;
                s[nt*2+1] += v.y; s2[nt*2+1] += v.y*v.y;
            }
        }
    }
    // reduce over the 8 lanes sharing (l&3) within the warp, then atomic
    #pragma unroll
    for (int off = 4; off < 32; off <<= 1){
        #pragma unroll
        for (int j = 0; j < 8; j++){
            s[j]  += __shfl_xor_sync(0xffffffffu, s[j],  off);
            s2[j] += __shfl_xor_sync(0xffffffffu, s2[j], off);
        }
    }
    if (l < 4){
        #pragma unroll
        for (int j = 0; j < 8; j++){
            int col = ni*32 + (j>>1)*8 + l*2 + (j&1);
            atomicAdd(&g_sum2[col], s[j]);
            atomicAdd(&g_sq2[col],  s2[j]);
        }
    }
}

// ---------------- kernel 5: act (+fin2 inline) ----------------
__global__ void k_act(const float* __restrict__ gma, const float* __restrict__ bta){
    __shared__ float smu[32], srs[32];
    int t = threadIdx.x;
    if (t < 32){
        float s  = g_sum2[2*t] + g_sum2[2*t+1];
        float s2 = g_sq2[2*t]  + g_sq2[2*t+1];
        float inv = 1.f/(float)(M_PTS*2);
        float mu = s*inv, var = s2*inv - mu*mu;
        smu[t] = mu; srs[t] = rsqrtf(var + 1e-5f);
    }
    __syncthreads();
    int i = blockIdx.x*256 + t;
    int c = i & 63; int g = c >> 1;
    float v = (g_mid[i] - smu[g])*srs[g]*gma[c] + bta[c];
    v = v / (1.f + expf(-v));
    g_act_h[i] = __float2half(v);
}

// ---------------- kernel 6: conv2 ----------------
__device__ __forceinline__ void conv2_issue(int tap, const int* s_pnbr, int t, char* dyn){
    char* base = dyn + (tap&1)*STG_BYTES;
    uint32_t bA = smem_u32(base);
    uint32_t bB = smem_u32(base + SMEM_A_BYTES);
    int rr = t>>3, c8 = t&7;
    int o = rr & 7;
    int tx = tap/9, ty = (tap/3)%3, tz = tap%3;
    int sx = ((o>>2)&1) + tx - 1, sy = ((o>>1)&1) + ty - 1, sz = (o&1) + tz - 1;
    int n3 = ((sx>>1)+1)*9 + ((sy>>1)+1)*3 + ((sz>>1)+1);
    int par = (sx&1)*4 + (sy&1)*2 + (sz&1);
    #pragma unroll
    for (int it = 0; it < 8; it++){
        int r = it*32 + rr;
        int pi = r>>3;
        int q = s_pnbr[pi*27 + n3];
        int nb = (q >= 0) ? q*8 + par : -1;
        const __half* src = (nb >= 0) ? &g_act_h[nb*CO + c8*8] : g_act_h;
        cp_async16(bA + r*(A_PAD*2) + c8*16, src, (nb >= 0) ? 16 : 0);
    }
    #pragma unroll
    for (int it = 0; it < 2; it++){
        int r = it*32 + rr;
        cp_async16(bB + r*(A_PAD*2) + c8*16, &g_w2t_h[(tap*CO + r)*CO + c8*8], 16);
    }
    CP_COMMIT();
}

__global__ __launch_bounds__(256,2) void k_conv2_mma(const int* __restrict__ coords,
                                                     const float* __restrict__ b2,
                                                     float* __restrict__ out){
    extern __shared__ __align__(16) char dyn[];
    __shared__ int s_pnbr[32*27];
    int t = threadIdx.x, l = t&31, w = t>>5;
    int m0 = blockIdx.x*256;
    int pbase = m0 >> 3;

    for (int e = t; e < 32*27; e += 256){
        int pl = e/27, n3 = e - pl*27;
        int p = pbase + pl;
        int ox = n3/9 - 1, oy = (n3/3)%3 - 1, oz = n3%3 - 1;
        int x = coords[p*4+1], y = coords[p*4+2], z = coords[p*4+3];
        s_pnbr[e] = g_pgrid[((x+ox+1)*GD + (y+oy+1))*GD + (z+oz+1)];
    }
    __syncthreads();

    conv2_issue(0, s_pnbr, t, dyn);

    float acc[16][4] = {};
    for (int tap = 0; tap < 27; tap++){
        if (tap + 1 < 27){ conv2_issue(tap+1, s_pnbr, t, dyn); CP_WAIT(1); }
        else             { CP_WAIT(0); }
        __syncthreads();
        char* base = dyn + (tap&1)*STG_BYTES;
        mma_chunk256(smem_u32(base), smem_u32(base + SMEM_A_BYTES), l, w, acc);
        __syncthreads();
    }

    int mi = w>>1, ni = w&1;
    #pragma unroll
    for (int mt = 0; mt < 4; mt++){
        #pragma unroll
        for (int nt = 0; nt < 4; nt++){
            float* ac = acc[mt*4+nt];
            int row0 = mi*64 + mt*16 + (l>>2);
            int col  = ni*32 + nt*8 + (l&3)*2;
            {
                int m = m0 + row0, p = m>>3;
                float2 v;
                v.x = ac[0] + b2[col]   + g_skip[p*CO + col];
                v.y = ac[1] + b2[col+1] + g_skip[p*CO + col+1];
                *(float2*)&out[(size_t)m*CO + col] = v;
            }
            {
                int m = m0 + row0 + 8, p = m>>3;
                float2 v;
                v.x = ac[2] + b2[col]   + g_skip[p*CO + col];
                v.y = ac[3] + b2[col+1] + g_skip[p*CO + col+1];
                *(float2*)&out[(size_t)m*CO + col] = v;
            }
        }
    }
}

// ---------------- launch ----------------
extern "C" void kernel_launch(void* const* d_in, const int* in_sizes, int n_in,
                              void* d_out, int out_size){
    const float* xf    = (const float*)d_in[0];
    const int*   coords= (const int*)  d_in[1];
    const float* gn1g  = (const float*)d_in[2];
    const float* gn1b  = (const float*)d_in[3];
    const float* W1    = (const float*)d_in[4];
    const float* b1    = (const float*)d_in[5];
    const float* gn2g  = (const float*)d_in[6];
    const float* gn2b  = (const float*)d_in[7];
    const float* W2    = (const float*)d_in[8];
    const float* b2    = (const float*)d_in[9];
    const float* Ws    = (const float*)d_in[10];
    const float* bs    = (const float*)d_in[11];
    float* out = (float*)d_out;

    static int attr_done = 0;
    if (!attr_done){
        cudaFuncSetAttribute(k_conv1_mma, cudaFuncAttributeMaxDynamicSharedMemorySize, SMEM_DYN);
        cudaFuncSetAttribute(k_conv2_mma, cudaFuncAttributeMaxDynamicSharedMemorySize, SMEM_DYN);
        attr_done = 1;
    }

    k_init<<<(GSZ+255)/256, 256>>>();
    k_front<<<239, 256>>>(coords, xf);
    k_prep<<<12480, 256>>>(W1, W2, xf, gn1g, gn1b);
    k_conv1_mma<<<dim3(79, 9), 256, SMEM_DYN>>>(coords, b1, xf, Ws, bs);
    k_act<<<M_PTS*CO/256, 256>>>(gn2g, gn2b);
    k_conv2_mma<<<M_PTS/256, 256, SMEM_DYN>>>(coords, b2, out);
}

// round 15
// speedup vs baseline: 2.8056x; 1.0127x over previous
#include <cuda_runtime.h>
#include <cuda_fp16.h>
#include <cstdint>
#include <math.h>

#define N_PTS 20000
#define M_PTS 160000
#define CI 128
#define CO 64
#define GD 34
#define GSZ (GD*GD*GD)

// stage: A 256x64 fp16 (row pad 72 halves = 144B), B 64x64 fp16 (same pad)
#define A_PAD 72
#define SMEM_A_BYTES (256*A_PAD*2)     // 36864
#define SMEM_B_BYTES (64*A_PAD*2)      // 9216
#define STG_BYTES (SMEM_A_BYTES + SMEM_B_BYTES)   // 46080
#define SMEM_DYN (2*STG_BYTES)                     // 92160

// ---------------- device scratch ----------------
__device__ int    g_pgrid[GSZ];
__device__ __align__(16) __half g_h_h[N_PTS*CI];       // silu(gn1(x)) fp16
__device__ float  g_skip[N_PTS*CO];
__device__ float  g_mid[M_PTS*CO];                     // conv1 out fp32
__device__ __align__(16) __half g_act_h[M_PTS*CO];     // silu(gn2(mid)) fp16
__device__ __align__(16) __half g_weffT_h[8*8*CO*CI];  // [o][n][cout][cin]
__device__ __align__(16) __half g_w2t_h[27*CO*CO];     // [tap][cout][cin]
__device__ float g_sum1[CI], g_sq1[CI];
__device__ float g_sum2[CO], g_sq2[CO];

// ---------------- helpers ----------------
__device__ __forceinline__ uint32_t smem_u32(const void* p){
    uint32_t a;
    asm("{ .reg .u64 t; cvta.to.shared.u64 t, %1; cvt.u32.u64 %0, t; }" : "=r"(a) : "l"(p));
    return a;
}
__device__ __forceinline__ void cp_async16(uint32_t dst, const void* src, int src_size){
    asm volatile("cp.async.ca.shared.global [%0], [%1], 16, %2;"
                 :: "r"(dst), "l"(src), "r"(src_size) : "memory");
}
#define CP_COMMIT() asm volatile("cp.async.commit_group;" ::: "memory")
#define CP_WAIT(n)  asm volatile("cp.async.wait_group %0;" :: "n"(n) : "memory")

__device__ __forceinline__ void ldsm4(uint32_t* r, uint32_t addr){
    asm volatile("ldmatrix.sync.aligned.m8n8.x4.shared.b16 {%0,%1,%2,%3}, [%4];"
        : "=r"(r[0]),"=r"(r[1]),"=r"(r[2]),"=r"(r[3]) : "r"(addr));
}
__device__ __forceinline__ void mma16816(float* d, const uint32_t* a, uint32_t b0, uint32_t b1){
    asm volatile("mma.sync.aligned.m16n8k16.row.col.f32.f16.f16.f32 "
        "{%0,%1,%2,%3}, {%4,%5,%6,%7}, {%8,%9}, {%0,%1,%2,%3};"
        : "+f"(d[0]),"+f"(d[1]),"+f"(d[2]),"+f"(d[3])
        : "r"(a[0]),"r"(a[1]),"r"(a[2]),"r"(a[3]), "r"(b0),"r"(b1));
}

// ---------------- kernel 1: init ----------------
__global__ void k_init(){
    int i = blockIdx.x*256 + threadIdx.x;
    if (i < GSZ) g_pgrid[i] = -1;
    if (i < CI){ g_sum1[i]=0.f; g_sq1[i]=0.f; }
    if (i < CO){ g_sum2[i]=0.f; g_sq2[i]=0.f; }
}

// ---------------- kernel 2: scatter + stats1 ----------------
__global__ void k_front(const int* __restrict__ coords, const float* __restrict__ xf){
    int b = blockIdx.x, t = threadIdx.x;
    if (b < 79){
        int p = b*256 + t;
        if (p < N_PTS){
            int x=coords[p*4+1], y=coords[p*4+2], z=coords[p*4+3];
            g_pgrid[((x+1)*GD + (y+1))*GD + (z+1)] = p;
        }
    } else {
        int bi = b - 79;                 // 0..159
        int c = t & 127;
        int sId = bi + 160*(t>>7);       // 0..319
        float s=0.f, s2=0.f;
        for (int r = sId; r < N_PTS; r += 320){
            float v = xf[r*CI + c]; s += v; s2 += v*v;
        }
        atomicAdd(&g_sum1[c], s); atomicAdd(&g_sq1[c], s2);
    }
}

// ---------------- kernel 3: prep = weffT | w2t | h(+fin1 inline) ----------------
__global__ void k_prep(const float* __restrict__ W1, const float* __restrict__ W2,
                       const float* __restrict__ xf,
                       const float* __restrict__ gma, const float* __restrict__ bta){
    int b = blockIdx.x, t = threadIdx.x;
    if (b < 2048){
        int idx = b*256 + t;   // 8*8*128*64
        int cout = idx & 63, cin = (idx>>6)&127, n = (idx>>13)&7, o = idx>>16;
        int d0=(o>>2)&1, d1=(o>>1)&1, d2=o&1;
        int n0=(n>>2)&1, n1=(n>>1)&1, n2=n&1;
        float s = 0.f;
        for (int i=0;i<3;i++){
            int t0=d0+i-1; int p0=(t0>=2)?1:((t0>=0)?0:-1);
            if (p0 - d0 + 1 != n0) continue;
            for (int j=0;j<3;j++){
                int t1=d1+j-1; int p1=(t1>=2)?1:((t1>=0)?0:-1);
                if (p1 - d1 + 1 != n1) continue;
                for (int k=0;k<3;k++){
                    int t2=d2+k-1; int p2=(t2>=2)?1:((t2>=0)?0:-1);
                    if (p2 - d2 + 1 != n2) continue;
                    s += W1[(((i*3+j)*3+k)*CI + cin)*CO + cout];
                }
            }
        }
        g_weffT_h[((o*8+n)*CO + cout)*CI + cin] = __float2half(s);
    } else if (b < 2480){
        int idx = (b-2048)*256 + t;   // 27*64*64 = 110592
        if (idx < 27*CO*CO){
            int cout = idx & 63, cin = (idx>>6)&63, tap = idx>>12;
            g_w2t_h[(tap*CO + cout)*CO + cin] = __float2half(W2[(tap*CO + cin)*CO + cout]);
        }
    } else {
        __shared__ float smu[32], srs[32];
        if (t < 32){
            float s=0.f, s2=0.f;
            #pragma unroll
            for (int j=0;j<4;j++){ s += g_sum1[t*4+j]; s2 += g_sq1[t*4+j]; }
            float inv = 1.f/(float)(N_PTS*4);
            float mu = s*inv, var = s2*inv - mu*mu;
            smu[t] = mu; srs[t] = rsqrtf(var + 1e-5f);
        }
        __syncthreads();
        int i = (b-2480)*256 + t;     // N_PTS*CI = 2560000, 10000 blocks exact
        int c = i & (CI-1); int g = c >> 2;
        float v = (xf[i] - smu[g])*srs[g]*gma[c] + bta[c];
        v = v / (1.f + expf(-v));
        g_h_h[i] = __float2half(v);
    }
}

// ---------------- skip tile (device fn, fp32 FFMA; runs in conv1 grid y==8) ----------------
__device__ __forceinline__ void mma_row(float4 a, float4 w0, float4 w1, float4 w2, float4 w3,
                                        float acc[4]){
    acc[0]=fmaf(a.x,w0.x,acc[0]); acc[0]=fmaf(a.y,w1.x,acc[0]); acc[0]=fmaf(a.z,w2.x,acc[0]); acc[0]=fmaf(a.w,w3.x,acc[0]);
    acc[1]=fmaf(a.x,w0.y,acc[1]); acc[1]=fmaf(a.y,w1.y,acc[1]); acc[1]=fmaf(a.z,w2.y,acc[1]); acc[1]=fmaf(a.w,w3.y,acc[1]);
    acc[2]=fmaf(a.x,w0.z,acc[2]); acc[2]=fmaf(a.y,w1.z,acc[2]); acc[2]=fmaf(a.z,w2.z,acc[2]); acc[2]=fmaf(a.w,w3.z,acc[2]);
    acc[3]=fmaf(a.x,w0.w,acc[3]); acc[3]=fmaf(a.y,w1.w,acc[3]); acc[3]=fmaf(a.z,w2.w,acc[3]); acc[3]=fmaf(a.w,w3.w,acc[3]);
}
__device__ void skip_tile(const float* __restrict__ xf, const float* __restrict__ Ws,
                          const float* __restrict__ bs, int p0, int t, char* dyn){
    float (*A_s)[68] = (float(*)[68])dyn;
    float (*W_s)[68] = (float(*)[68])(dyn + 64*68*4);
    float acc[4][4] = {};
    int tr = t>>4, tc = t&15;
    for (int ck = 0; ck < 2; ck++){
        __syncthreads();
        #pragma unroll
        for (int rep = 0; rep < 4; rep++){
            int idx = rep*256 + t;
            int r = idx>>4, kv = idx&15;
            int p = p0 + r;
            float4 v = make_float4(0.f,0.f,0.f,0.f);
            if (p < N_PTS) v = *(const float4*)&xf[p*CI + ck*64 + kv*4];
            *(float4*)&A_s[r][kv*4] = v;
            *(float4*)&W_s[r][kv*4] = *(const float4*)&Ws[(ck*64 + r)*CO + kv*4];
        }
        __syncthreads();
        #pragma unroll
        for (int kk = 0; kk < 64; kk += 4){
            float4 w0 = *(float4*)&W_s[kk+0][tc*4];
            float4 w1 = *(float4*)&W_s[kk+1][tc*4];
            float4 w2 = *(float4*)&W_s[kk+2][tc*4];
            float4 w3 = *(float4*)&W_s[kk+3][tc*4];
            #pragma unroll
            for (int i = 0; i < 4; i++){
                float4 a = *(float4*)&A_s[tr*4+i][kk];
                mma_row(a, w0, w1, w2, w3, acc[i]);
            }
        }
    }
    #pragma unroll
    for (int i = 0; i < 4; i++){
        int p = p0 + tr*4 + i;
        if (p < N_PTS){
            float4 r;
            r.x = acc[i][0] + bs[tc*4+0];
            r.y = acc[i][1] + bs[tc*4+1];
            r.z = acc[i][2] + bs[tc*4+2];
            r.w = acc[i][3] + bs[tc*4+3];
            *(float4*)&g_skip[p*CO + tc*4] = r;
        }
    }
}

// ---------------- MMA on one staged chunk: A[256][64] x B^T[64][64] fp16 ----------------
// Lane mapping (A and B): lanes 0-15 -> rows +0..15 at col base; lanes 16-31 -> same rows
// at col base +16B. ldsm4 regs: [ (r0-7,k0-7), (r8-15,k0-7), (r0-7,k8-15), (r8-15,k8-15) ]
// => B n8-fragments pair {b[0],b[2]} and {b[1],b[3]}.
__device__ __forceinline__ void mma_chunk256(uint32_t bA, uint32_t bB, int l, int w,
                                             float acc[16][4]){
    int mi = w>>1, ni = w&1;
    int lr = l&15, lc = l>>4;
    #pragma unroll
    for (int ks = 0; ks < 4; ks++){
        int colb = ks*32 + lc*16;
        uint32_t a[4][4];
        #pragma unroll
        for (int mt = 0; mt < 4; mt++){
            int row = mi*64 + mt*16 + lr;
            ldsm4(a[mt], bA + row*(A_PAD*2) + colb);
        }
        #pragma unroll
        for (int bt = 0; bt < 2; bt++){
            uint32_t b[4];
            int brow = ni*32 + bt*16 + lr;
            ldsm4(b, bB + brow*(A_PAD*2) + colb);
            #pragma unroll
            for (int mt = 0; mt < 4; mt++){
                mma16816(acc[mt*4 + bt*2],     a[mt], b[0], b[2]);
                mma16816(acc[mt*4 + bt*2 + 1], a[mt], b[1], b[3]);
            }
        }
    }
}

// ---------------- kernel 4: conv1 (+ skip on y==8, + stats2 in epilogue) ----------------
// One __syncthreads per chunk: sync(st) proves all warps finished mma(st-1), which is the
// reader of the buffer issue(st+1) overwrites. issue(st+1) precedes mma(st) so the next
// chunk's LDG overlaps this chunk's MMAs; CP_WAIT(0) at iteration top awaits it.
__device__ __forceinline__ void conv1_issue(int st, int o, const int* s_nbr, int t, char* dyn){
    int n = st>>1, ck = st&1;
    char* base = dyn + (st&1)*STG_BYTES;
    uint32_t bA = smem_u32(base);
    uint32_t bB = smem_u32(base + SMEM_A_BYTES);
    int rr = t>>3, c8 = t&7;
    #pragma unroll
    for (int it = 0; it < 8; it++){
        int r = it*32 + rr;
        int nb = s_nbr[n*256 + r];
        const __half* src = (nb >= 0) ? &g_h_h[nb*CI + ck*64 + c8*8] : g_h_h;
        cp_async16(bA + r*(A_PAD*2) + c8*16, src, (nb >= 0) ? 16 : 0);
    }
    #pragma unroll
    for (int it = 0; it < 2; it++){
        int r = it*32 + rr;
        cp_async16(bB + r*(A_PAD*2) + c8*16,
                   &g_weffT_h[((o*8+n)*CO + r)*CI + ck*64 + c8*8], 16);
    }
    CP_COMMIT();
}

__global__ __launch_bounds__(256,2) void k_conv1_mma(const int* __restrict__ coords,
                                                     const float* __restrict__ b1,
                                                     const float* __restrict__ xf,
                                                     const float* __restrict__ Ws,
                                                     const float* __restrict__ bs){
    extern __shared__ __align__(16) char dyn[];
    __shared__ int s_nbr[8*256];
    int t = threadIdx.x, l = t&31, w = t>>5;

    if (blockIdx.y == 8){   // skip GEMM filler: 79 blocks x 256 rows
        #pragma unroll
        for (int c = 0; c < 4; c++)
            skip_tile(xf, Ws, bs, blockIdx.x*256 + c*64, t, dyn);
        return;
    }

    int p0 = blockIdx.x*256;
    int o  = blockIdx.y;
    int dx=(o>>2)&1, dy=(o>>1)&1, dz=o&1;

    {
        int p = p0 + t;
        if (p < N_PTS){
            int x=coords[p*4+1], y=coords[p*4+2], z=coords[p*4+3];
            #pragma unroll
            for (int n = 0; n < 8; n++){
                int ox = dx-1+((n>>2)&1), oy = dy-1+((n>>1)&1), oz = dz-1+(n&1);
                s_nbr[n*256 + t] = g_pgrid[((x+ox+1)*GD + (y+oy+1))*GD + (z+oz+1)];
            }
        } else {
            #pragma unroll
            for (int n = 0; n < 8; n++) s_nbr[n*256 + t] = -1;
        }
    }
    __syncthreads();

    conv1_issue(0, o, s_nbr, t, dyn);

    float acc[16][4] = {};
    for (int st = 0; st < 16; st++){
        CP_WAIT(0);
        __syncthreads();
        if (st + 1 < 16) conv1_issue(st+1, o, s_nbr, t, dyn);
        char* base = dyn + (st&1)*STG_BYTES;
        mma_chunk256(smem_u32(base), smem_u32(base + SMEM_A_BYTES), l, w, acc);
    }

    int mi = w>>1, ni = w&1;
    float s[8] = {}, s2[8] = {};
    #pragma unroll
    for (int mt = 0; mt < 4; mt++){
        #pragma unroll
        for (int nt = 0; nt < 4; nt++){
            float* ac = acc[mt*4+nt];
            int row0 = mi*64 + mt*16 + (l>>2);
            int col  = ni*32 + nt*8 + (l&3)*2;
            int p_0 = p0 + row0;
            if (p_0 < N_PTS){
                float2 v; v.x = ac[0] + b1[col]; v.y = ac[1] + b1[col+1];
                *(float2*)&g_mid[((size_t)p_0*8 + o)*CO + col] = v;
                s[nt*2+0] += v.x; s2[nt*2+0] += v.x*v.x;
                s[nt*2+1] += v.y; s2[nt*2+1] += v.y*v.y;
            }
            int p_1 = p0 + row0 + 8;
            if (p_1 < N_PTS){
                float2 v; v.x = ac[2] + b1[col]; v.y = ac[3] + b1[col+1];
                *(float2*)&g_mid[((size_t)p_1*8 + o)*CO + col] = v;
                s[nt*2+0] += v.x; s2[nt*2+0] += v.x*v.x;
                s[nt*2+1] += v.y; s2[nt*2+1] += v.y*v.y;
            }
        }
    }
    #pragma unroll
    for (int off = 4; off < 32; off <<= 1){
        #pragma unroll
        for (int j = 0; j < 8; j++){
            s[j]  += __shfl_xor_sync(0xffffffffu, s[j],  off);
            s2[j] += __shfl_xor_sync(0xffffffffu, s2[j], off);
        }
    }
    if (l < 4){
        #pragma unroll
        for (int j = 0; j < 8; j++){
            int col = ni*32 + (j>>1)*8 + l*2 + (j&1);
            atomicAdd(&g_sum2[col], s[j]);
            atomicAdd(&g_sq2[col],  s2[j]);
        }
    }
}

// ---------------- kernel 5: act (+fin2 inline) ----------------
__global__ void k_act(const float* __restrict__ gma, const float* __restrict__ bta){
    __shared__ float smu[32], srs[32];
    int t = threadIdx.x;
    if (t < 32){
        float s  = g_sum2[2*t] + g_sum2[2*t+1];
        float s2 = g_sq2[2*t]  + g_sq2[2*t+1];
        float inv = 1.f/(float)(M_PTS*2);
        float mu = s*inv, var = s2*inv - mu*mu;
        smu[t] = mu; srs[t] = rsqrtf(var + 1e-5f);
    }
    __syncthreads();
    int i = blockIdx.x*256 + t;
    int c = i & 63; int g = c >> 1;
    float v = (g_mid[i] - smu[g])*srs[g]*gma[c] + bta[c];
    v = v / (1.f + expf(-v));
    g_act_h[i] = __float2half(v);
}

// ---------------- kernel 6: conv2 ----------------
__device__ __forceinline__ void conv2_issue(int tap, const int* s_pnbr, int t, char* dyn){
    char* base = dyn + (tap&1)*STG_BYTES;
    uint32_t bA = smem_u32(base);
    uint32_t bB = smem_u32(base + SMEM_A_BYTES);
    int rr = t>>3, c8 = t&7;
    int o = rr & 7;
    int tx = tap/9, ty = (tap/3)%3, tz = tap%3;
    int sx = ((o>>2)&1) + tx - 1, sy = ((o>>1)&1) + ty - 1, sz = (o&1) + tz - 1;
    int n3 = ((sx>>1)+1)*9 + ((sy>>1)+1)*3 + ((sz>>1)+1);
    int par = (sx&1)*4 + (sy&1)*2 + (sz&1);
    #pragma unroll
    for (int it = 0; it < 8; it++){
        int r = it*32 + rr;
        int pi = r>>3;
        int q = s_pnbr[pi*27 + n3];
        int nb = (q >= 0) ? q*8 + par : -1;
        const __half* src = (nb >= 0) ? &g_act_h[nb*CO + c8*8] : g_act_h;
        cp_async16(bA + r*(A_PAD*2) + c8*16, src, (nb >= 0) ? 16 : 0);
    }
    #pragma unroll
    for (int it = 0; it < 2; it++){
        int r = it*32 + rr;
        cp_async16(bB + r*(A_PAD*2) + c8*16, &g_w2t_h[(tap*CO + r)*CO + c8*8], 16);
    }
    CP_COMMIT();
}

__global__ __launch_bounds__(256,2) void k_conv2_mma(const int* __restrict__ coords,
                                                     const float* __restrict__ b2,
                                                     float* __restrict__ out){
    extern __shared__ __align__(16) char dyn[];
    __shared__ int s_pnbr[32*27];
    int t = threadIdx.x, l = t&31, w = t>>5;
    int m0 = blockIdx.x*256;
    int pbase = m0 >> 3;

    for (int e = t; e < 32*27; e += 256){
        int pl = e/27, n3 = e - pl*27;
        int p = pbase + pl;
        int ox = n3/9 - 1, oy = (n3/3)%3 - 1, oz = n3%3 - 1;
        int x = coords[p*4+1], y = coords[p*4+2], z = coords[p*4+3];
        s_pnbr[e] = g_pgrid[((x+ox+1)*GD + (y+oy+1))*GD + (z+oz+1)];
    }
    __syncthreads();

    conv2_issue(0, s_pnbr, t, dyn);

    float acc[16][4] = {};
    for (int tap = 0; tap < 27; tap++){
        CP_WAIT(0);
        __syncthreads();
        if (tap + 1 < 27) conv2_issue(tap+1, s_pnbr, t, dyn);
        char* base = dyn + (tap&1)*STG_BYTES;
        mma_chunk256(smem_u32(base), smem_u32(base + SMEM_A_BYTES), l, w, acc);
    }

    int mi = w>>1, ni = w&1;
    #pragma unroll
    for (int mt = 0; mt < 4; mt++){
        #pragma unroll
        for (int nt = 0; nt < 4; nt++){
            float* ac = acc[mt*4+nt];
            int row0 = mi*64 + mt*16 + (l>>2);
            int col  = ni*32 + nt*8 + (l&3)*2;
            {
                int m = m0 + row0, p = m>>3;
                float2 v;
                v.x = ac[0] + b2[col]   + g_skip[p*CO + col];
                v.y = ac[1] + b2[col+1] + g_skip[p*CO + col+1];
                *(float2*)&out[(size_t)m*CO + col] = v;
            }
            {
                int m = m0 + row0 + 8, p = m>>3;
                float2 v;
                v.x = ac[2] + b2[col]   + g_skip[p*CO + col];
                v.y = ac[3] + b2[col+1] + g_skip[p*CO + col+1];
                *(float2*)&out[(size_t)m*CO + col] = v;
            }
        }
    }
}

// ---------------- launch ----------------
extern "C" void kernel_launch(void* const* d_in, const int* in_sizes, int n_in,
                              void* d_out, int out_size){
    const float* xf    = (const float*)d_in[0];
    const int*   coords= (const int*)  d_in[1];
    const float* gn1g  = (const float*)d_in[2];
    const float* gn1b  = (const float*)d_in[3];
    const float* W1    = (const float*)d_in[4];
    const float* b1    = (const float*)d_in[5];
    const float* gn2g  = (const float*)d_in[6];
    const float* gn2b  = (const float*)d_in[7];
    const float* W2    = (const float*)d_in[8];
    const float* b2    = (const float*)d_in[9];
    const float* Ws    = (const float*)d_in[10];
    const float* bs    = (const float*)d_in[11];
    float* out = (float*)d_out;

    static int attr_done = 0;
    if (!attr_done){
        cudaFuncSetAttribute(k_conv1_mma, cudaFuncAttributeMaxDynamicSharedMemorySize, SMEM_DYN);
        cudaFuncSetAttribute(k_conv2_mma, cudaFuncAttributeMaxDynamicSharedMemorySize, SMEM_DYN);
        attr_done = 1;
    }

    k_init<<<(GSZ+255)/256, 256>>>();
    k_front<<<239, 256>>>(coords, xf);
    k_prep<<<12480, 256>>>(W1, W2, xf, gn1g, gn1b);
    k_conv1_mma<<<dim3(79, 9), 256, SMEM_DYN>>>(coords, b1, xf, Ws, bs);
    k_act<<<M_PTS*CO/256, 256>>>(gn2g, gn2b);
    k_conv2_mma<<<M_PTS/256, 256, SMEM_DYN>>>(coords, b2, out);
}